// round 11
// baseline (speedup 1.0000x reference)
#include <cuda_runtime.h>
#include <math.h>

// Problem constants
#define BQ 2
#define SQ 2048
#define EQ 1024
#define HQ 16
#define DQ 64
#define MQ 256
#define KTOP 64
#define EPSF 1e-6f

// ---------------- device scratch (no cudaMalloc allowed) ----------------
__device__ float g_Qs[BQ*SQ*EQ];
__device__ float g_Ks[BQ*SQ*EQ];
__device__ float g_Vs[BQ*SQ*EQ];
__device__ float g_Qp[BQ*SQ*EQ];
__device__ float g_Kp[BQ*SQ*EQ];
__device__ float g_Vp[BQ*SQ*EQ];
__device__ float g_scores[(size_t)BQ*HQ*SQ*SQ];      // 512 MB
__device__ float g_merged_s[BQ*SQ*EQ];
__device__ float g_merged_p[BQ*SQ*EQ];
__device__ float g_out_s[BQ*SQ*EQ];
__device__ float g_out_p[BQ*SQ*EQ];
__device__ float g_phi_q[BQ*HQ*SQ*MQ];
__device__ float g_phi_k[BQ*HQ*SQ*MQ];
__device__ float g_kv[BQ*HQ*MQ*DQ];
__device__ float g_z[BQ*HQ*MQ];
__device__ float g_avg[BQ*EQ];
__device__ float g_gate[BQ*2];

// ---------------- generic fp32 SGEMM (NN) 128x128x16, 8x8/thread ----------------
__global__ __launch_bounds__(256) void sgemm_nn(const float* __restrict__ A,
                                                const float* __restrict__ Bm,
                                                const float* __restrict__ bias,
                                                float* __restrict__ C,
                                                int Mn, int Nn, int Kn) {
    __shared__ float As[16][132];
    __shared__ float Bs[16][128];
    int tid = threadIdx.x;
    int m0 = blockIdx.y * 128, n0 = blockIdx.x * 128;
    int tx = tid & 15, ty = tid >> 4;
    float acc[8][8];
#pragma unroll
    for (int i = 0; i < 8; i++)
#pragma unroll
        for (int j = 0; j < 8; j++) acc[i][j] = 0.f;

    for (int k0 = 0; k0 < Kn; k0 += 16) {
#pragma unroll
        for (int r = 0; r < 2; r++) {
            int idx = tid + r * 256;
            int ar = idx >> 2;
            int ac = (idx & 3) * 4;
            float4 v = *(const float4*)(A + (size_t)(m0 + ar) * Kn + k0 + ac);
            As[ac + 0][ar] = v.x; As[ac + 1][ar] = v.y;
            As[ac + 2][ar] = v.z; As[ac + 3][ar] = v.w;
        }
#pragma unroll
        for (int r = 0; r < 2; r++) {
            int idx = tid + r * 256;
            int br = idx >> 5;
            int bc = (idx & 31) * 4;
            *(float4*)&Bs[br][bc] = *(const float4*)(Bm + (size_t)(k0 + br) * Nn + n0 + bc);
        }
        __syncthreads();
#pragma unroll
        for (int kk = 0; kk < 16; kk++) {
            float a[8], b[8];
            *(float4*)a       = *(float4*)&As[kk][ty * 8];
            *(float4*)(a + 4) = *(float4*)&As[kk][ty * 8 + 4];
            *(float4*)b       = *(float4*)&Bs[kk][tx * 8];
            *(float4*)(b + 4) = *(float4*)&Bs[kk][tx * 8 + 4];
#pragma unroll
            for (int i = 0; i < 8; i++)
#pragma unroll
                for (int j = 0; j < 8; j++) acc[i][j] += a[i] * b[j];
        }
        __syncthreads();
    }
    float bv[8];
#pragma unroll
    for (int j = 0; j < 8; j++) bv[j] = bias ? bias[n0 + tx * 8 + j] : 0.f;
    float* Cb = C + (size_t)(m0 + ty * 8) * Nn + n0 + tx * 8;
#pragma unroll
    for (int i = 0; i < 8; i++) {
        float4 o0 = make_float4(acc[i][0] + bv[0], acc[i][1] + bv[1], acc[i][2] + bv[2], acc[i][3] + bv[3]);
        float4 o1 = make_float4(acc[i][4] + bv[4], acc[i][5] + bv[5], acc[i][6] + bv[6], acc[i][7] + bv[7]);
        *(float4*)(Cb + (size_t)i * Nn)     = o0;
        *(float4*)(Cb + (size_t)i * Nn + 4) = o1;
    }
}

// ---------------- scores = 0.125 * Q K^T (batched over b,h) ----------------
__global__ __launch_bounds__(256) void score_kernel(const float* __restrict__ Q,
                                                    const float* __restrict__ Kc,
                                                    float* __restrict__ Sc) {
    __shared__ float Qs[32][132];
    __shared__ float Ks[32][132];
    int tid = threadIdx.x;
    int bh = blockIdx.z;
    int b = bh >> 4, h = bh & 15;
    int q0 = blockIdx.y * 128, k0 = blockIdx.x * 128;
    int tx = tid & 15, ty = tid >> 4;
    float acc[8][8];
#pragma unroll
    for (int i = 0; i < 8; i++)
#pragma unroll
        for (int j = 0; j < 8; j++) acc[i][j] = 0.f;

    const float* Qb = Q + ((size_t)b * SQ + q0) * EQ + h * DQ;
    const float* Kb = Kc + ((size_t)b * SQ + k0) * EQ + h * DQ;

    for (int dc = 0; dc < 64; dc += 32) {
#pragma unroll
        for (int r = 0; r < 4; r++) {
            int idx = tid + r * 256;
            int rr = idx >> 3;
            int cc = (idx & 7) * 4;
            float4 qv = *(const float4*)(Qb + (size_t)rr * EQ + dc + cc);
            Qs[cc + 0][rr] = qv.x; Qs[cc + 1][rr] = qv.y;
            Qs[cc + 2][rr] = qv.z; Qs[cc + 3][rr] = qv.w;
            float4 kv = *(const float4*)(Kb + (size_t)rr * EQ + dc + cc);
            Ks[cc + 0][rr] = kv.x; Ks[cc + 1][rr] = kv.y;
            Ks[cc + 2][rr] = kv.z; Ks[cc + 3][rr] = kv.w;
        }
        __syncthreads();
#pragma unroll
        for (int kk = 0; kk < 32; kk++) {
            float a[8], bb[8];
            *(float4*)a        = *(float4*)&Qs[kk][ty * 8];
            *(float4*)(a + 4)  = *(float4*)&Qs[kk][ty * 8 + 4];
            *(float4*)bb       = *(float4*)&Ks[kk][tx * 8];
            *(float4*)(bb + 4) = *(float4*)&Ks[kk][tx * 8 + 4];
#pragma unroll
            for (int i = 0; i < 8; i++)
#pragma unroll
                for (int j = 0; j < 8; j++) acc[i][j] += a[i] * bb[j];
        }
        __syncthreads();
    }
    float* Cb = Sc + ((size_t)bh * SQ + q0) * SQ + k0;
#pragma unroll
    for (int i = 0; i < 8; i++) {
        float4 o0 = make_float4(acc[i][0] * 0.125f, acc[i][1] * 0.125f, acc[i][2] * 0.125f, acc[i][3] * 0.125f);
        float4 o1 = make_float4(acc[i][4] * 0.125f, acc[i][5] * 0.125f, acc[i][6] * 0.125f, acc[i][7] * 0.125f);
        *(float4*)(Cb + (size_t)(ty * 8 + i) * SQ + tx * 8)     = o0;
        *(float4*)(Cb + (size_t)(ty * 8 + i) * SQ + tx * 8 + 4) = o1;
    }
}

// ---------------- fused top-64 select + masked softmax + P*V gather ----------------
__device__ __forceinline__ unsigned fkey(float f) {
    unsigned u = __float_as_uint(f);
    return (u & 0x80000000u) ? ~u : (u | 0x80000000u);
}

#define CAPL 1024
__global__ __launch_bounds__(256) void topk_pv_kernel(const float* __restrict__ Sc,
                                                      const float* __restrict__ V,
                                                      float* __restrict__ Mrg) {
    __shared__ float row[2048];
    __shared__ unsigned hist[256];
    __shared__ float red[256];
    __shared__ int   s_idx[CAPL];
    __shared__ float s_p[CAPL];
    __shared__ float outacc[64];
    __shared__ unsigned s_prefix;
    __shared__ int s_want;
    __shared__ int s_cnt;

    int tid = threadIdx.x;
    int rrow = blockIdx.x;           // global row: bh*2048 + q
    int bh = rrow >> 11;
    int q = rrow & 2047;
    int b = bh >> 4, h = bh & 15;

    const float* src = Sc + (size_t)rrow * 2048;
    float lmax = -3.4e38f;
#pragma unroll
    for (int t = 0; t < 8; t++) {
        int i = tid + t * 256;
        float v = src[i];
        row[i] = v;
        lmax = fmaxf(lmax, v);
    }
    red[tid] = lmax;
    __syncthreads();
    for (int s = 128; s > 0; s >>= 1) {
        if (tid < s) red[tid] = fmaxf(red[tid], red[tid + s]);
        __syncthreads();
    }
    float rowmax = red[0];
    __syncthreads();

    // MSD radix select: key of 64th-largest element
    unsigned prefix = 0;
    int want = KTOP;
    for (int pass = 3; pass >= 0; pass--) {
        hist[tid] = 0;
        __syncthreads();
        int shift = pass * 8;
        unsigned himask = (pass == 3) ? 0u : (0xFFFFFFFFu << (8 * (pass + 1)));
#pragma unroll
        for (int t = 0; t < 8; t++) {
            int i = tid + t * 256;
            unsigned u = fkey(row[i]);
            if ((u & himask) == prefix) atomicAdd(&hist[(u >> shift) & 255], 1u);
        }
        __syncthreads();
        if (tid == 0) {
            unsigned cum = 0;
            for (int bin = 255; bin >= 0; bin--) {
                unsigned c = hist[bin];
                if (cum + c >= (unsigned)want) {
                    s_prefix = prefix | ((unsigned)bin << shift);
                    s_want = want - (int)cum;
                    break;
                }
                cum += c;
            }
        }
        __syncthreads();
        prefix = s_prefix;
        want = s_want;
        __syncthreads();
    }
    unsigned tk = prefix;

    if (tid == 0) s_cnt = 0;
    __syncthreads();
#pragma unroll
    for (int t = 0; t < 8; t++) {
        int i = tid + t * 256;
        float v = row[i];
        if (fkey(v) >= tk) {
            int p = atomicAdd(&s_cnt, 1);
            if (p < CAPL) { s_idx[p] = i; s_p[p] = expf(v - rowmax); }
        }
    }
    __syncthreads();
    int cnt = s_cnt;

    float* dst = Mrg + ((size_t)(b * SQ + q)) * EQ + h * DQ;
    const float* Vb = V + (size_t)b * SQ * EQ + h * DQ;

    if (cnt <= CAPL) {
        float ps = 0.f;
        for (int j = tid; j < cnt; j += 256) ps += s_p[j];
        red[tid] = ps;
        __syncthreads();
        for (int s = 128; s > 0; s >>= 1) {
            if (tid < s) red[tid] += red[tid + s];
            __syncthreads();
        }
        float sum = red[0];
        if (tid < 64) {
            float a = 0.f;
#pragma unroll 4
            for (int j = 0; j < cnt; j++)
                a += s_p[j] * Vb[(size_t)s_idx[j] * EQ + tid];
            dst[tid] = a / sum;
        }
    } else {
        // pathological tie-overflow fallback (exact, dense)
        if (tid < 64) outacc[tid] = 0.f;
        float ps = 0.f;
#pragma unroll
        for (int t = 0; t < 8; t++) {
            int i = tid + t * 256;
            float v = row[i];
            if (fkey(v) >= tk) ps += expf(v - rowmax);
        }
        red[tid] = ps;
        __syncthreads();
        for (int s = 128; s > 0; s >>= 1) {
            if (tid < s) red[tid] += red[tid + s];
            __syncthreads();
        }
        float sum = red[0];
        int d = tid & 63, seg = tid >> 6;
        float a = 0.f;
        for (int i = seg * 512; i < seg * 512 + 512; i++) {
            float v = row[i];
            if (fkey(v) >= tk) a += expf(v - rowmax) * Vb[(size_t)i * EQ + d];
        }
        atomicAdd(&outacc[d], a);
        __syncthreads();
        if (tid < 64) dst[tid] = outacc[tid] / sum;
    }
}

// ---------------- performer: phi = relu(q @ Wfeat) + eps ----------------
__global__ __launch_bounds__(256) void phi_kernel(const float* __restrict__ Qp,
                                                  const float* __restrict__ Wf,
                                                  float* __restrict__ Phi) {
    __shared__ float Qt[32][132];
    __shared__ float Wt[32][64];
    int tid = threadIdx.x;
    int m0 = blockIdx.x * 64, s0 = blockIdx.y * 128, bh = blockIdx.z;
    int b = bh >> 4, h = bh & 15;
    int tx = tid & 15, ty = tid >> 4;
    float acc[8][4];
#pragma unroll
    for (int i = 0; i < 8; i++)
#pragma unroll
        for (int j = 0; j < 4; j++) acc[i][j] = 0.f;

    const float* Qb = Qp + ((size_t)b * SQ + s0) * EQ + h * DQ;
    for (int dc = 0; dc < 64; dc += 32) {
#pragma unroll
        for (int r = 0; r < 4; r++) {
            int idx = tid + r * 256;
            int rr = idx >> 3;
            int cc = (idx & 7) * 4;
            float4 v = *(const float4*)(Qb + (size_t)rr * EQ + dc + cc);
            Qt[cc + 0][rr] = v.x; Qt[cc + 1][rr] = v.y;
            Qt[cc + 2][rr] = v.z; Qt[cc + 3][rr] = v.w;
        }
#pragma unroll
        for (int r = 0; r < 2; r++) {
            int idx = tid + r * 256;
            int rr = idx >> 4;
            int cc = (idx & 15) * 4;
            *(float4*)&Wt[rr][cc] = *(const float4*)(Wf + (size_t)(dc + rr) * MQ + m0 + cc);
        }
        __syncthreads();
#pragma unroll
        for (int kk = 0; kk < 32; kk++) {
            float a[8], w[4];
            *(float4*)a       = *(float4*)&Qt[kk][ty * 8];
            *(float4*)(a + 4) = *(float4*)&Qt[kk][ty * 8 + 4];
            *(float4*)w       = *(float4*)&Wt[kk][tx * 4];
#pragma unroll
            for (int i = 0; i < 8; i++)
#pragma unroll
                for (int j = 0; j < 4; j++) acc[i][j] += a[i] * w[j];
        }
        __syncthreads();
    }
    float* Pb = Phi + ((size_t)bh * SQ + s0) * MQ + m0;
#pragma unroll
    for (int i = 0; i < 8; i++) {
        float4 o = make_float4(fmaxf(acc[i][0], 0.f) + EPSF, fmaxf(acc[i][1], 0.f) + EPSF,
                               fmaxf(acc[i][2], 0.f) + EPSF, fmaxf(acc[i][3], 0.f) + EPSF);
        *(float4*)(Pb + (size_t)(ty * 8 + i) * MQ + tx * 4) = o;
    }
}

// ---------------- kv[m,d] = sum_s phi_k[s,m] v[s,d]; z[m] = sum_s phi_k[s,m] ----------------
__global__ __launch_bounds__(256) void kv_kernel(const float* __restrict__ Phik,
                                                 const float* __restrict__ Vp,
                                                 float* __restrict__ KV,
                                                 float* __restrict__ Z) {
    __shared__ float Ph[16][64];
    __shared__ float Vv[16][64];
    int tid = threadIdx.x;
    int m0 = blockIdx.x * 64, bh = blockIdx.y;
    int b = bh >> 4, h = bh & 15;
    int td = tid & 15, tm = tid >> 4;
    float acc[4][4];
    float zacc[4];
#pragma unroll
    for (int i = 0; i < 4; i++) {
        zacc[i] = 0.f;
#pragma unroll
        for (int j = 0; j < 4; j++) acc[i][j] = 0.f;
    }
    for (int s0 = 0; s0 < SQ; s0 += 16) {
        int rr = tid >> 4, cc = (tid & 15) * 4;
        *(float4*)&Ph[rr][cc] = *(const float4*)(Phik + ((size_t)bh * SQ + s0 + rr) * MQ + m0 + cc);
        *(float4*)&Vv[rr][cc] = *(const float4*)(Vp + ((size_t)(b * SQ + s0 + rr)) * EQ + h * DQ + cc);
        __syncthreads();
#pragma unroll
        for (int ss = 0; ss < 16; ss++) {
            float pm[4], vv[4];
            *(float4*)pm = *(float4*)&Ph[ss][tm * 4];
            *(float4*)vv = *(float4*)&Vv[ss][td * 4];
#pragma unroll
            for (int i = 0; i < 4; i++)
#pragma unroll
                for (int j = 0; j < 4; j++) acc[i][j] += pm[i] * vv[j];
            if (td == 0) {
#pragma unroll
                for (int i = 0; i < 4; i++) zacc[i] += pm[i];
            }
        }
        __syncthreads();
    }
#pragma unroll
    for (int i = 0; i < 4; i++)
#pragma unroll
        for (int j = 0; j < 4; j++)
            KV[(size_t)bh * MQ * DQ + (size_t)(m0 + tm * 4 + i) * DQ + td * 4 + j] = acc[i][j];
    if (td == 0) {
#pragma unroll
        for (int i = 0; i < 4; i++) Z[(size_t)bh * MQ + m0 + tm * 4 + i] = zacc[i];
    }
}

// ---------------- num/den: out = (phi_q @ kv) / (phi_q @ z + eps) -> merged layout ----------------
__global__ __launch_bounds__(256) void numden_kernel(const float* __restrict__ Phiq,
                                                     const float* __restrict__ KV,
                                                     const float* __restrict__ Z,
                                                     float* __restrict__ Out) {
    __shared__ float Pt[32][132];
    __shared__ float Kv[32][64];
    __shared__ float zk[32];
    int tid = threadIdx.x;
    int s0 = blockIdx.x * 128, bh = blockIdx.y;
    int b = bh >> 4, h = bh & 15;
    int tx = tid & 15, ty = tid >> 4;
    float acc[8][4];
    float den[8];
#pragma unroll
    for (int i = 0; i < 8; i++) {
        den[i] = 0.f;
#pragma unroll
        for (int j = 0; j < 4; j++) acc[i][j] = 0.f;
    }
    for (int kc = 0; kc < MQ; kc += 32) {
#pragma unroll
        for (int r = 0; r < 4; r++) {
            int idx = tid + r * 256;
            int rr = idx >> 3;
            int cc = (idx & 7) * 4;
            float4 v = *(const float4*)(Phiq + ((size_t)bh * SQ + s0 + rr) * MQ + kc + cc);
            Pt[cc + 0][rr] = v.x; Pt[cc + 1][rr] = v.y;
            Pt[cc + 2][rr] = v.z; Pt[cc + 3][rr] = v.w;
        }
#pragma unroll
        for (int r = 0; r < 2; r++) {
            int idx = tid + r * 256;
            int rr = idx >> 4;
            int cc = (idx & 15) * 4;
            *(float4*)&Kv[rr][cc] = *(const float4*)(KV + (size_t)bh * MQ * DQ + (size_t)(kc + rr) * DQ + cc);
        }
        if (tid < 32) zk[tid] = Z[(size_t)bh * MQ + kc + tid];
        __syncthreads();
#pragma unroll
        for (int kk = 0; kk < 32; kk++) {
            float a[8], w[4];
            *(float4*)a       = *(float4*)&Pt[kk][ty * 8];
            *(float4*)(a + 4) = *(float4*)&Pt[kk][ty * 8 + 4];
            *(float4*)w       = *(float4*)&Kv[kk][tx * 4];
            float zz = zk[kk];
#pragma unroll
            for (int i = 0; i < 8; i++) {
                den[i] += a[i] * zz;
#pragma unroll
                for (int j = 0; j < 4; j++) acc[i][j] += a[i] * w[j];
            }
        }
        __syncthreads();
    }
#pragma unroll
    for (int i = 0; i < 8; i++) {
        float inv = 1.f / (den[i] + EPSF);
        float4 o = make_float4(acc[i][0] * inv, acc[i][1] * inv, acc[i][2] * inv, acc[i][3] * inv);
        *(float4*)(Out + ((size_t)(b * SQ + s0 + ty * 8 + i)) * EQ + h * DQ + tx * 4) = o;
    }
}

// ---------------- gating ----------------
__global__ void avg_kernel(const float* __restrict__ x, float* __restrict__ Avg) {
    int b = blockIdx.x;
    int e = blockIdx.y * 256 + threadIdx.x;
    float s = 0.f;
    for (int t = 0; t < SQ; t++) s += x[((size_t)b * SQ + t) * EQ + e];
    Avg[b * EQ + e] = s * (1.f / SQ);
}

__global__ void gate_kernel(const float* __restrict__ Avg, const float* __restrict__ Wg,
                            const float* __restrict__ bg, float* __restrict__ Gate) {
    __shared__ float red[256];
    __shared__ float lg[2][2];
    int tid = threadIdx.x;
    float p[2][2] = {{0.f, 0.f}, {0.f, 0.f}};
    for (int e = tid; e < EQ; e += 256) {
        float w0 = Wg[e * 2], w1 = Wg[e * 2 + 1];
        for (int b = 0; b < 2; b++) {
            float a = Avg[b * EQ + e];
            p[b][0] += a * w0;
            p[b][1] += a * w1;
        }
    }
    for (int b = 0; b < 2; b++)
        for (int j = 0; j < 2; j++) {
            red[tid] = p[b][j];
            __syncthreads();
            for (int s = 128; s > 0; s >>= 1) {
                if (tid < s) red[tid] += red[tid + s];
                __syncthreads();
            }
            if (tid == 0) lg[b][j] = red[0] + bg[j];
            __syncthreads();
        }
    if (tid == 0) {
        for (int b = 0; b < 2; b++) {
            float m = fmaxf(lg[b][0], lg[b][1]);
            float e0 = expf(lg[b][0] - m), e1 = expf(lg[b][1] - m);
            float inv = 1.f / (e0 + e1);
            Gate[b * 2]     = e0 * inv;
            Gate[b * 2 + 1] = e1 * inv;
        }
    }
}

__global__ void combine_kernel(const float* __restrict__ Os, const float* __restrict__ Op,
                               const float* __restrict__ Gate, float* __restrict__ Out) {
    size_t i = (size_t)blockIdx.x * 256 + threadIdx.x;
    int b = (int)(i >> 21);   // SQ*EQ = 2^21
    Out[i] = Gate[b * 2] * Os[i] + Gate[b * 2 + 1] * Op[i];
}

// ---------------- host launcher ----------------
extern "C" void kernel_launch(void* const* d_in, const int* in_sizes, int n_in,
                              void* d_out, int out_size) {
    const float* x    = (const float*)d_in[0];
    const float* Wq_s = (const float*)d_in[1];
    const float* Wk_s = (const float*)d_in[2];
    const float* Wv_s = (const float*)d_in[3];
    const float* Wo_s = (const float*)d_in[4];
    const float* bq_s = (const float*)d_in[5];
    const float* bk_s = (const float*)d_in[6];
    const float* bv_s = (const float*)d_in[7];
    const float* bo_s = (const float*)d_in[8];
    const float* Wq_p = (const float*)d_in[9];
    const float* Wk_p = (const float*)d_in[10];
    const float* Wv_p = (const float*)d_in[11];
    const float* Wo_p = (const float*)d_in[12];
    const float* bo_p = (const float*)d_in[13];
    const float* Wfeat = (const float*)d_in[14];
    const float* Wg   = (const float*)d_in[15];
    const float* bg   = (const float*)d_in[16];
    float* out = (float*)d_out;

    float *Qs, *Ks, *Vs, *Qp, *Kp, *Vp, *Scr, *MrgS, *MrgP, *Os, *Op;
    float *Pq, *Pk, *KVb, *Zb, *Av, *Gt;
    cudaGetSymbolAddress((void**)&Qs,   g_Qs);
    cudaGetSymbolAddress((void**)&Ks,   g_Ks);
    cudaGetSymbolAddress((void**)&Vs,   g_Vs);
    cudaGetSymbolAddress((void**)&Qp,   g_Qp);
    cudaGetSymbolAddress((void**)&Kp,   g_Kp);
    cudaGetSymbolAddress((void**)&Vp,   g_Vp);
    cudaGetSymbolAddress((void**)&Scr,  g_scores);
    cudaGetSymbolAddress((void**)&MrgS, g_merged_s);
    cudaGetSymbolAddress((void**)&MrgP, g_merged_p);
    cudaGetSymbolAddress((void**)&Os,   g_out_s);
    cudaGetSymbolAddress((void**)&Op,   g_out_p);
    cudaGetSymbolAddress((void**)&Pq,   g_phi_q);
    cudaGetSymbolAddress((void**)&Pk,   g_phi_k);
    cudaGetSymbolAddress((void**)&KVb,  g_kv);
    cudaGetSymbolAddress((void**)&Zb,   g_z);
    cudaGetSymbolAddress((void**)&Av,   g_avg);
    cudaGetSymbolAddress((void**)&Gt,   g_gate);

    const int MT = BQ * SQ;  // 4096 token rows
    dim3 gemmGrid(EQ / 128, MT / 128);  // (8, 32)

    // projections (sparse branch has q/k/v biases; performer q/k/v have none)
    sgemm_nn<<<gemmGrid, 256>>>(x, Wq_s, bq_s, Qs, MT, EQ, EQ);
    sgemm_nn<<<gemmGrid, 256>>>(x, Wk_s, bk_s, Ks, MT, EQ, EQ);
    sgemm_nn<<<gemmGrid, 256>>>(x, Wv_s, bv_s, Vs, MT, EQ, EQ);
    sgemm_nn<<<gemmGrid, 256>>>(x, Wq_p, nullptr, Qp, MT, EQ, EQ);
    sgemm_nn<<<gemmGrid, 256>>>(x, Wk_p, nullptr, Kp, MT, EQ, EQ);
    sgemm_nn<<<gemmGrid, 256>>>(x, Wv_p, nullptr, Vp, MT, EQ, EQ);

    // sparse branch
    score_kernel<<<dim3(SQ / 128, SQ / 128, BQ * HQ), 256>>>(Qs, Ks, Scr);
    topk_pv_kernel<<<BQ * HQ * SQ, 256>>>(Scr, Vs, MrgS);
    sgemm_nn<<<gemmGrid, 256>>>(MrgS, Wo_s, bo_s, Os, MT, EQ, EQ);

    // performer branch
    phi_kernel<<<dim3(MQ / 64, SQ / 128, BQ * HQ), 256>>>(Qp, Wfeat, Pq);
    phi_kernel<<<dim3(MQ / 64, SQ / 128, BQ * HQ), 256>>>(Kp, Wfeat, Pk);
    kv_kernel<<<dim3(MQ / 64, BQ * HQ), 256>>>(Pk, Vp, KVb, Zb);
    numden_kernel<<<dim3(SQ / 128, BQ * HQ), 256>>>(Pq, KVb, Zb, MrgP);
    sgemm_nn<<<gemmGrid, 256>>>(MrgP, Wo_p, bo_p, Op, MT, EQ, EQ);

    // gate + combine
    avg_kernel<<<dim3(BQ, EQ / 256), 256>>>(x, Av);
    gate_kernel<<<1, 256>>>(Av, Wg, bg, Gt);
    combine_kernel<<<(BQ * SQ * EQ) / 256, 256>>>(Os, Op, Gt, out);
}

// round 16
// speedup vs baseline: 1.1053x; 1.1053x over previous
#include <cuda_runtime.h>
#include <cuda_bf16.h>
#include <mma.h>
#include <math.h>
#include <stdint.h>

using namespace nvcuda;

// Problem constants
#define BQ 2
#define SQ 2048
#define EQ 1024
#define HQ 16
#define DQ 64
#define MQ 256
#define KTOP 64
#define EPSF 1e-6f

// ---------------- device scratch (no cudaMalloc allowed) ----------------
__device__ float g_Qs[BQ*SQ*EQ];
__device__ float g_Ks[BQ*SQ*EQ];
__device__ float g_Vs[BQ*SQ*EQ];
__device__ float g_Qp[BQ*SQ*EQ];
__device__ float g_Kp[BQ*SQ*EQ];
__device__ float g_Vp[BQ*SQ*EQ];
__device__ float g_scores[(size_t)BQ*HQ*SQ*SQ];      // 512 MB
__device__ float g_merged_s[BQ*SQ*EQ];
__device__ float g_merged_p[BQ*SQ*EQ];
__device__ float g_out_s[BQ*SQ*EQ];
__device__ float g_out_p[BQ*SQ*EQ];
__device__ float g_phi_q[BQ*HQ*SQ*MQ];
__device__ float g_phi_k[BQ*HQ*SQ*MQ];
__device__ float g_kv[BQ*HQ*MQ*DQ];
__device__ float g_z[BQ*HQ*MQ];
__device__ float g_avg[BQ*EQ];
__device__ float g_gate[BQ*2];

// bf16 hi/lo split scratch (off-selection-path GEMMs only)
__device__ __align__(16) __nv_bfloat16 g_ahi[BQ*SQ*EQ];
__device__ __align__(16) __nv_bfloat16 g_alo[BQ*SQ*EQ];
__device__ __align__(16) __nv_bfloat16 g_wthi[6*EQ*EQ];   // transposed weights [n][k]
__device__ __align__(16) __nv_bfloat16 g_wtlo[6*EQ*EQ];

// ---------------- fp32 SGEMM (NN) 128x128x16, 8x8/thread — EXACT path ----------------
__global__ __launch_bounds__(256) void sgemm_nn(const float* __restrict__ A,
                                                const float* __restrict__ Bm,
                                                const float* __restrict__ bias,
                                                float* __restrict__ C,
                                                int Mn, int Nn, int Kn) {
    __shared__ float As[16][132];
    __shared__ float Bs[16][128];
    int tid = threadIdx.x;
    int m0 = blockIdx.y * 128, n0 = blockIdx.x * 128;
    int tx = tid & 15, ty = tid >> 4;
    float acc[8][8];
#pragma unroll
    for (int i = 0; i < 8; i++)
#pragma unroll
        for (int j = 0; j < 8; j++) acc[i][j] = 0.f;

    for (int k0 = 0; k0 < Kn; k0 += 16) {
#pragma unroll
        for (int r = 0; r < 2; r++) {
            int idx = tid + r * 256;
            int ar = idx >> 2;
            int ac = (idx & 3) * 4;
            float4 v = *(const float4*)(A + (size_t)(m0 + ar) * Kn + k0 + ac);
            As[ac + 0][ar] = v.x; As[ac + 1][ar] = v.y;
            As[ac + 2][ar] = v.z; As[ac + 3][ar] = v.w;
        }
#pragma unroll
        for (int r = 0; r < 2; r++) {
            int idx = tid + r * 256;
            int br = idx >> 5;
            int bc = (idx & 31) * 4;
            *(float4*)&Bs[br][bc] = *(const float4*)(Bm + (size_t)(k0 + br) * Nn + n0 + bc);
        }
        __syncthreads();
#pragma unroll
        for (int kk = 0; kk < 16; kk++) {
            float a[8], b[8];
            *(float4*)a       = *(float4*)&As[kk][ty * 8];
            *(float4*)(a + 4) = *(float4*)&As[kk][ty * 8 + 4];
            *(float4*)b       = *(float4*)&Bs[kk][tx * 8];
            *(float4*)(b + 4) = *(float4*)&Bs[kk][tx * 8 + 4];
#pragma unroll
            for (int i = 0; i < 8; i++)
#pragma unroll
                for (int j = 0; j < 8; j++) acc[i][j] += a[i] * b[j];
        }
        __syncthreads();
    }
    float bv[8];
#pragma unroll
    for (int j = 0; j < 8; j++) bv[j] = bias ? bias[n0 + tx * 8 + j] : 0.f;
    float* Cb = C + (size_t)(m0 + ty * 8) * Nn + n0 + tx * 8;
#pragma unroll
    for (int i = 0; i < 8; i++) {
        float4 o0 = make_float4(acc[i][0] + bv[0], acc[i][1] + bv[1], acc[i][2] + bv[2], acc[i][3] + bv[3]);
        float4 o1 = make_float4(acc[i][4] + bv[4], acc[i][5] + bv[5], acc[i][6] + bv[6], acc[i][7] + bv[7]);
        *(float4*)(Cb + (size_t)i * Nn)     = o0;
        *(float4*)(Cb + (size_t)i * Nn + 4) = o1;
    }
}

// ---------------- scores = 0.125 * Q K^T (fp32, EXACT — selection path) ----------------
__global__ __launch_bounds__(256) void score_kernel(const float* __restrict__ Q,
                                                    const float* __restrict__ Kc,
                                                    float* __restrict__ Sc) {
    __shared__ float Qs[32][132];
    __shared__ float Ks[32][132];
    int tid = threadIdx.x;
    int bh = blockIdx.z;
    int b = bh >> 4, h = bh & 15;
    int q0 = blockIdx.y * 128, k0 = blockIdx.x * 128;
    int tx = tid & 15, ty = tid >> 4;
    float acc[8][8];
#pragma unroll
    for (int i = 0; i < 8; i++)
#pragma unroll
        for (int j = 0; j < 8; j++) acc[i][j] = 0.f;

    const float* Qb = Q + ((size_t)b * SQ + q0) * EQ + h * DQ;
    const float* Kb = Kc + ((size_t)b * SQ + k0) * EQ + h * DQ;

    for (int dc = 0; dc < 64; dc += 32) {
#pragma unroll
        for (int r = 0; r < 4; r++) {
            int idx = tid + r * 256;
            int rr = idx >> 3;
            int cc = (idx & 7) * 4;
            float4 qv = *(const float4*)(Qb + (size_t)rr * EQ + dc + cc);
            Qs[cc + 0][rr] = qv.x; Qs[cc + 1][rr] = qv.y;
            Qs[cc + 2][rr] = qv.z; Qs[cc + 3][rr] = qv.w;
            float4 kv = *(const float4*)(Kb + (size_t)rr * EQ + dc + cc);
            Ks[cc + 0][rr] = kv.x; Ks[cc + 1][rr] = kv.y;
            Ks[cc + 2][rr] = kv.z; Ks[cc + 3][rr] = kv.w;
        }
        __syncthreads();
#pragma unroll
        for (int kk = 0; kk < 32; kk++) {
            float a[8], bb[8];
            *(float4*)a        = *(float4*)&Qs[kk][ty * 8];
            *(float4*)(a + 4)  = *(float4*)&Qs[kk][ty * 8 + 4];
            *(float4*)bb       = *(float4*)&Ks[kk][tx * 8];
            *(float4*)(bb + 4) = *(float4*)&Ks[kk][tx * 8 + 4];
#pragma unroll
            for (int i = 0; i < 8; i++)
#pragma unroll
                for (int j = 0; j < 8; j++) acc[i][j] += a[i] * bb[j];
        }
        __syncthreads();
    }
    float* Cb = Sc + ((size_t)bh * SQ + q0) * SQ + k0;
#pragma unroll
    for (int i = 0; i < 8; i++) {
        float4 o0 = make_float4(acc[i][0] * 0.125f, acc[i][1] * 0.125f, acc[i][2] * 0.125f, acc[i][3] * 0.125f);
        float4 o1 = make_float4(acc[i][4] * 0.125f, acc[i][5] * 0.125f, acc[i][6] * 0.125f, acc[i][7] * 0.125f);
        *(float4*)(Cb + (size_t)(ty * 8 + i) * SQ + tx * 8)     = o0;
        *(float4*)(Cb + (size_t)(ty * 8 + i) * SQ + tx * 8 + 4) = o1;
    }
}

// =============== WMMA bf16 split-2 GEMM (C = A.Bt) — benign-precision path ======
#define SLD 48
__global__ __launch_bounds__(256) void gemm_wmma(
    const __nv_bfloat16* __restrict__ Ahi, const __nv_bfloat16* __restrict__ Alo,
    int lda,
    const __nv_bfloat16* __restrict__ Bhi, const __nv_bfloat16* __restrict__ Blo,
    int ldb,
    float* __restrict__ C, int ldc, int Ktot)
{
    __shared__ __align__(32) __nv_bfloat16 sAh[128 * SLD];
    __shared__ __align__(32) __nv_bfloat16 sAl[128 * SLD];
    __shared__ __align__(32) __nv_bfloat16 sBh[128 * SLD];
    __shared__ __align__(32) __nv_bfloat16 sBl[128 * SLD];

    int tid = threadIdx.x, wid = tid >> 5;
    int m0 = blockIdx.y * 128, n0 = blockIdx.x * 128;
    int wm = (wid & 3) * 32;
    int wn = (wid >> 2) * 64;

    wmma::fragment<wmma::accumulator, 16, 16, 16, float> acc[2][4];
#pragma unroll
    for (int i = 0; i < 2; i++)
#pragma unroll
        for (int j = 0; j < 4; j++) wmma::fill_fragment(acc[i][j], 0.f);

    for (int kc = 0; kc < Ktot; kc += 32) {
#pragma unroll
        for (int it = 0; it < 2; it++) {
            int idx = tid + it * 256;
            int r = idx >> 2, c8 = (idx & 3) * 8;
            size_t ga = (size_t)(m0 + r) * lda + kc + c8;
            size_t gb = (size_t)(n0 + r) * ldb + kc + c8;
            *(uint4*)(sAh + r * SLD + c8) = *(const uint4*)(Ahi + ga);
            *(uint4*)(sAl + r * SLD + c8) = *(const uint4*)(Alo + ga);
            *(uint4*)(sBh + r * SLD + c8) = *(const uint4*)(Bhi + gb);
            *(uint4*)(sBl + r * SLD + c8) = *(const uint4*)(Blo + gb);
        }
        __syncthreads();

#pragma unroll
        for (int ko = 0; ko < 32; ko += 16) {
            wmma::fragment<wmma::matrix_a, 16, 16, 16, __nv_bfloat16, wmma::row_major> ah[2], al[2];
            wmma::fragment<wmma::matrix_b, 16, 16, 16, __nv_bfloat16, wmma::col_major> bh[4], bl[4];
#pragma unroll
            for (int i = 0; i < 2; i++) {
                wmma::load_matrix_sync(ah[i], sAh + (wm + i * 16) * SLD + ko, SLD);
                wmma::load_matrix_sync(al[i], sAl + (wm + i * 16) * SLD + ko, SLD);
            }
#pragma unroll
            for (int j = 0; j < 4; j++) {
                wmma::load_matrix_sync(bh[j], sBh + (wn + j * 16) * SLD + ko, SLD);
                wmma::load_matrix_sync(bl[j], sBl + (wn + j * 16) * SLD + ko, SLD);
            }
#pragma unroll
            for (int i = 0; i < 2; i++)
#pragma unroll
                for (int j = 0; j < 4; j++) {
                    wmma::mma_sync(acc[i][j], ah[i], bh[j], acc[i][j]);
                    wmma::mma_sync(acc[i][j], ah[i], bl[j], acc[i][j]);
                    wmma::mma_sync(acc[i][j], al[i], bh[j], acc[i][j]);
                }
        }
        __syncthreads();
    }

#pragma unroll
    for (int i = 0; i < 2; i++)
#pragma unroll
        for (int j = 0; j < 4; j++)
            wmma::store_matrix_sync(C + (size_t)(m0 + wm + i * 16) * ldc + n0 + wn + j * 16,
                                    acc[i][j], ldc, wmma::mem_row_major);
}

// bias add: C[m][n] += bias[n]
__global__ void bias_add(float* __restrict__ C, const float* __restrict__ bias) {
    size_t i = ((size_t)blockIdx.x * 256 + threadIdx.x) * 4;
    int n = (int)(i & (EQ - 1));
    float4 c = *(float4*)(C + i);
    float4 bv = *(const float4*)(bias + n);
    c.x += bv.x; c.y += bv.y; c.z += bv.z; c.w += bv.w;
    *(float4*)(C + i) = c;
}

// =============== hi/lo conversion kernels ===============
__device__ __forceinline__ void split1(float v, __nv_bfloat16& h, __nv_bfloat16& l) {
    h = __float2bfloat16(v);
    l = __float2bfloat16(v - __bfloat162float(h));
}

__global__ void split_fp32(const float* __restrict__ in,
                           __nv_bfloat16* __restrict__ hi, __nv_bfloat16* __restrict__ lo) {
    size_t i = (size_t)blockIdx.x * 256 + threadIdx.x;
    float4 v = ((const float4*)in)[i];
    __nv_bfloat16 h[4], l[4];
    split1(v.x, h[0], l[0]); split1(v.y, h[1], l[1]);
    split1(v.z, h[2], l[2]); split1(v.w, h[3], l[3]);
    *(uint2*)(hi + i * 4) = *(uint2*)h;
    *(uint2*)(lo + i * 4) = *(uint2*)l;
}

// W[k][n] fp32 -> T[n][k] bf16 hi/lo
__global__ void wtrans_split(const float* __restrict__ W,
                             __nv_bfloat16* __restrict__ Thi, __nv_bfloat16* __restrict__ Tlo) {
    __shared__ float t[32][33];
    int n0 = blockIdx.x * 32, k0 = blockIdx.y * 32;
    int tx = threadIdx.x & 31, ty = threadIdx.x >> 5;
#pragma unroll
    for (int r = 0; r < 32; r += 8)
        t[ty + r][tx] = W[(size_t)(k0 + ty + r) * EQ + n0 + tx];
    __syncthreads();
#pragma unroll
    for (int r = 0; r < 32; r += 8) {
        float v = t[tx][ty + r];
        size_t o = (size_t)(n0 + ty + r) * EQ + k0 + tx;
        __nv_bfloat16 h, l;
        split1(v, h, l);
        Thi[o] = h; Tlo[o] = l;
    }
}

// ---------------- fused top-64 select + masked softmax + P*V gather ----------------
__device__ __forceinline__ unsigned fkey(float f) {
    unsigned u = __float_as_uint(f);
    return (u & 0x80000000u) ? ~u : (u | 0x80000000u);
}

#define CAPL 1024
__global__ __launch_bounds__(256) void topk_pv_kernel(const float* __restrict__ Sc,
                                                      const float* __restrict__ V,
                                                      float* __restrict__ Mrg) {
    __shared__ float row[2048];
    __shared__ unsigned hist[256];
    __shared__ float red[256];
    __shared__ int   s_idx[CAPL];
    __shared__ float s_p[CAPL];
    __shared__ float outacc[64];
    __shared__ unsigned s_prefix;
    __shared__ int s_want;
    __shared__ int s_cnt;

    int tid = threadIdx.x;
    int rrow = blockIdx.x;
    int bh = rrow >> 11;
    int q = rrow & 2047;
    int b = bh >> 4, h = bh & 15;

    const float* src = Sc + (size_t)rrow * 2048;
    float lmax = -3.4e38f;
#pragma unroll
    for (int t = 0; t < 8; t++) {
        int i = tid + t * 256;
        float v = src[i];
        row[i] = v;
        lmax = fmaxf(lmax, v);
    }
    red[tid] = lmax;
    __syncthreads();
    for (int s = 128; s > 0; s >>= 1) {
        if (tid < s) red[tid] = fmaxf(red[tid], red[tid + s]);
        __syncthreads();
    }
    float rowmax = red[0];
    __syncthreads();

    unsigned prefix = 0;
    int want = KTOP;
    for (int pass = 3; pass >= 0; pass--) {
        hist[tid] = 0;
        __syncthreads();
        int shift = pass * 8;
        unsigned himask = (pass == 3) ? 0u : (0xFFFFFFFFu << (8 * (pass + 1)));
#pragma unroll
        for (int t = 0; t < 8; t++) {
            int i = tid + t * 256;
            unsigned u = fkey(row[i]);
            if ((u & himask) == prefix) atomicAdd(&hist[(u >> shift) & 255], 1u);
        }
        __syncthreads();
        if (tid == 0) {
            unsigned cum = 0;
            for (int bin = 255; bin >= 0; bin--) {
                unsigned c = hist[bin];
                if (cum + c >= (unsigned)want) {
                    s_prefix = prefix | ((unsigned)bin << shift);
                    s_want = want - (int)cum;
                    break;
                }
                cum += c;
            }
        }
        __syncthreads();
        prefix = s_prefix;
        want = s_want;
        __syncthreads();
    }
    unsigned tk = prefix;

    if (tid == 0) s_cnt = 0;
    __syncthreads();
#pragma unroll
    for (int t = 0; t < 8; t++) {
        int i = tid + t * 256;
        float v = row[i];
        if (fkey(v) >= tk) {
            int p = atomicAdd(&s_cnt, 1);
            if (p < CAPL) { s_idx[p] = i; s_p[p] = expf(v - rowmax); }
        }
    }
    __syncthreads();
    int cnt = s_cnt;

    float* dst = Mrg + ((size_t)(b * SQ + q)) * EQ + h * DQ;
    const float* Vb = V + (size_t)b * SQ * EQ + h * DQ;

    if (cnt <= CAPL) {
        float ps = 0.f;
        for (int j = tid; j < cnt; j += 256) ps += s_p[j];
        red[tid] = ps;
        __syncthreads();
        for (int s = 128; s > 0; s >>= 1) {
            if (tid < s) red[tid] += red[tid + s];
            __syncthreads();
        }
        float sum = red[0];
        if (tid < 64) {
            float a = 0.f;
#pragma unroll 4
            for (int j = 0; j < cnt; j++)
                a += s_p[j] * Vb[(size_t)s_idx[j] * EQ + tid];
            dst[tid] = a / sum;
        }
    } else {
        if (tid < 64) outacc[tid] = 0.f;
        float ps = 0.f;
#pragma unroll
        for (int t = 0; t < 8; t++) {
            int i = tid + t * 256;
            float v = row[i];
            if (fkey(v) >= tk) ps += expf(v - rowmax);
        }
        red[tid] = ps;
        __syncthreads();
        for (int s = 128; s > 0; s >>= 1) {
            if (tid < s) red[tid] += red[tid + s];
            __syncthreads();
        }
        float sum = red[0];
        int d = tid & 63, seg = tid >> 6;
        float a = 0.f;
        for (int i = seg * 512; i < seg * 512 + 512; i++) {
            float v = row[i];
            if (fkey(v) >= tk) a += expf(v - rowmax) * Vb[(size_t)i * EQ + d];
        }
        atomicAdd(&outacc[d], a);
        __syncthreads();
        if (tid < 64) dst[tid] = outacc[tid] / sum;
    }
}

// ---------------- performer: phi = relu(q @ Wfeat) + eps ----------------
__global__ __launch_bounds__(256) void phi_kernel(const float* __restrict__ Qp,
                                                  const float* __restrict__ Wf,
                                                  float* __restrict__ Phi) {
    __shared__ float Qt[32][132];
    __shared__ float Wt[32][64];
    int tid = threadIdx.x;
    int m0 = blockIdx.x * 64, s0 = blockIdx.y * 128, bh = blockIdx.z;
    int b = bh >> 4, h = bh & 15;
    int tx = tid & 15, ty = tid >> 4;
    float acc[8][4];
#pragma unroll
    for (int i = 0; i < 8; i++)
#pragma unroll
        for (int j = 0; j < 4; j++) acc[i][j] = 0.f;

    const float* Qb = Qp + ((size_t)b * SQ + s0) * EQ + h * DQ;
    for (int dc = 0; dc < 64; dc += 32) {
#pragma unroll
        for (int r = 0; r < 4; r++) {
            int idx = tid + r * 256;
            int rr = idx >> 3;
            int cc = (idx & 7) * 4;
            float4 v = *(const float4*)(Qb + (size_t)rr * EQ + dc + cc);
            Qt[cc + 0][rr] = v.x; Qt[cc + 1][rr] = v.y;
            Qt[cc + 2][rr] = v.z; Qt[cc + 3][rr] = v.w;
        }
#pragma unroll
        for (int r = 0; r < 2; r++) {
            int idx = tid + r * 256;
            int rr = idx >> 4;
            int cc = (idx & 15) * 4;
            *(float4*)&Wt[rr][cc] = *(const float4*)(Wf + (size_t)(dc + rr) * MQ + m0 + cc);
        }
        __syncthreads();
#pragma unroll
        for (int kk = 0; kk < 32; kk++) {
            float a[8], w[4];
            *(float4*)a       = *(float4*)&Qt[kk][ty * 8];
            *(float4*)(a + 4) = *(float4*)&Qt[kk][ty * 8 + 4];
            *(float4*)w       = *(float4*)&Wt[kk][tx * 4];
#pragma unroll
            for (int i = 0; i < 8; i++)
#pragma unroll
                for (int j = 0; j < 4; j++) acc[i][j] += a[i] * w[j];
        }
        __syncthreads();
    }
    float* Pb = Phi + ((size_t)bh * SQ + s0) * MQ + m0;
#pragma unroll
    for (int i = 0; i < 8; i++) {
        float4 o = make_float4(fmaxf(acc[i][0], 0.f) + EPSF, fmaxf(acc[i][1], 0.f) + EPSF,
                               fmaxf(acc[i][2], 0.f) + EPSF, fmaxf(acc[i][3], 0.f) + EPSF);
        *(float4*)(Pb + (size_t)(ty * 8 + i) * MQ + tx * 4) = o;
    }
}

// ---------------- kv + z ----------------
__global__ __launch_bounds__(256) void kv_kernel(const float* __restrict__ Phik,
                                                 const float* __restrict__ Vp,
                                                 float* __restrict__ KV,
                                                 float* __restrict__ Z) {
    __shared__ float Ph[16][64];
    __shared__ float Vv[16][64];
    int tid = threadIdx.x;
    int m0 = blockIdx.x * 64, bh = blockIdx.y;
    int b = bh >> 4, h = bh & 15;
    int td = tid & 15, tm = tid >> 4;
    float acc[4][4];
    float zacc[4];
#pragma unroll
    for (int i = 0; i < 4; i++) {
        zacc[i] = 0.f;
#pragma unroll
        for (int j = 0; j < 4; j++) acc[i][j] = 0.f;
    }
    for (int s0 = 0; s0 < SQ; s0 += 16) {
        int rr = tid >> 4, cc = (tid & 15) * 4;
        *(float4*)&Ph[rr][cc] = *(const float4*)(Phik + ((size_t)bh * SQ + s0 + rr) * MQ + m0 + cc);
        *(float4*)&Vv[rr][cc] = *(const float4*)(Vp + ((size_t)(b * SQ + s0 + rr)) * EQ + h * DQ + cc);
        __syncthreads();
#pragma unroll
        for (int ss = 0; ss < 16; ss++) {
            float pm[4], vv[4];
            *(float4*)pm = *(float4*)&Ph[ss][tm * 4];
            *(float4*)vv = *(float4*)&Vv[ss][td * 4];
#pragma unroll
            for (int i = 0; i < 4; i++)
#pragma unroll
                for (int j = 0; j < 4; j++) acc[i][j] += pm[i] * vv[j];
            if (td == 0) {
#pragma unroll
                for (int i = 0; i < 4; i++) zacc[i] += pm[i];
            }
        }
        __syncthreads();
    }
#pragma unroll
    for (int i = 0; i < 4; i++)
#pragma unroll
        for (int j = 0; j < 4; j++)
            KV[(size_t)bh * MQ * DQ + (size_t)(m0 + tm * 4 + i) * DQ + td * 4 + j] = acc[i][j];
    if (td == 0) {
#pragma unroll
        for (int i = 0; i < 4; i++) Z[(size_t)bh * MQ + m0 + tm * 4 + i] = zacc[i];
    }
}

// ---------------- num/den ----------------
__global__ __launch_bounds__(256) void numden_kernel(const float* __restrict__ Phiq,
                                                     const float* __restrict__ KV,
                                                     const float* __restrict__ Z,
                                                     float* __restrict__ Out) {
    __shared__ float Pt[32][132];
    __shared__ float Kv[32][64];
    __shared__ float zk[32];
    int tid = threadIdx.x;
    int s0 = blockIdx.x * 128, bh = blockIdx.y;
    int b = bh >> 4, h = bh & 15;
    int tx = tid & 15, ty = tid >> 4;
    float acc[8][4];
    float den[8];
#pragma unroll
    for (int i = 0; i < 8; i++) {
        den[i] = 0.f;
#pragma unroll
        for (int j = 0; j < 4; j++) acc[i][j] = 0.f;
    }
    for (int kc = 0; kc < MQ; kc += 32) {
#pragma unroll
        for (int r = 0; r < 4; r++) {
            int idx = tid + r * 256;
            int rr = idx >> 3;
            int cc = (idx & 7) * 4;
            float4 v = *(const float4*)(Phiq + ((size_t)bh * SQ + s0 + rr) * MQ + kc + cc);
            Pt[cc + 0][rr] = v.x; Pt[cc + 1][rr] = v.y;
            Pt[cc + 2][rr] = v.z; Pt[cc + 3][rr] = v.w;
        }
#pragma unroll
        for (int r = 0; r < 2; r++) {
            int idx = tid + r * 256;
            int rr = idx >> 4;
            int cc = (idx & 15) * 4;
            *(float4*)&Kv[rr][cc] = *(const float4*)(KV + (size_t)bh * MQ * DQ + (size_t)(kc + rr) * DQ + cc);
        }
        if (tid < 32) zk[tid] = Z[(size_t)bh * MQ + kc + tid];
        __syncthreads();
#pragma unroll
        for (int kk = 0; kk < 32; kk++) {
            float a[8], w[4];
            *(float4*)a       = *(float4*)&Pt[kk][ty * 8];
            *(float4*)(a + 4) = *(float4*)&Pt[kk][ty * 8 + 4];
            *(float4*)w       = *(float4*)&Kv[kk][tx * 4];
            float zz = zk[kk];
#pragma unroll
            for (int i = 0; i < 8; i++) {
                den[i] += a[i] * zz;
#pragma unroll
                for (int j = 0; j < 4; j++) acc[i][j] += a[i] * w[j];
            }
        }
        __syncthreads();
    }
#pragma unroll
    for (int i = 0; i < 8; i++) {
        float inv = 1.f / (den[i] + EPSF);
        float4 o = make_float4(acc[i][0] * inv, acc[i][1] * inv, acc[i][2] * inv, acc[i][3] * inv);
        *(float4*)(Out + ((size_t)(b * SQ + s0 + ty * 8 + i)) * EQ + h * DQ + tx * 4) = o;
    }
}

// ---------------- gating ----------------
__global__ void avg_kernel(const float* __restrict__ x, float* __restrict__ Avg) {
    int b = blockIdx.x;
    int e = blockIdx.y * 256 + threadIdx.x;
    float s = 0.f;
    for (int t = 0; t < SQ; t++) s += x[((size_t)b * SQ + t) * EQ + e];
    Avg[b * EQ + e] = s * (1.f / SQ);
}

__global__ void gate_kernel(const float* __restrict__ Avg, const float* __restrict__ Wg,
                            const float* __restrict__ bg, float* __restrict__ Gate) {
    __shared__ float red[256];
    __shared__ float lg[2][2];
    int tid = threadIdx.x;
    float p[2][2] = {{0.f, 0.f}, {0.f, 0.f}};
    for (int e = tid; e < EQ; e += 256) {
        float w0 = Wg[e * 2], w1 = Wg[e * 2 + 1];
        for (int b = 0; b < 2; b++) {
            float a = Avg[b * EQ + e];
            p[b][0] += a * w0;
            p[b][1] += a * w1;
        }
    }
    for (int b = 0; b < 2; b++)
        for (int j = 0; j < 2; j++) {
            red[tid] = p[b][j];
            __syncthreads();
            for (int s = 128; s > 0; s >>= 1) {
                if (tid < s) red[tid] += red[tid + s];
                __syncthreads();
            }
            if (tid == 0) lg[b][j] = red[0] + bg[j];
            __syncthreads();
        }
    if (tid == 0) {
        for (int b = 0; b < 2; b++) {
            float m = fmaxf(lg[b][0], lg[b][1]);
            float e0 = expf(lg[b][0] - m), e1 = expf(lg[b][1] - m);
            float inv = 1.f / (e0 + e1);
            Gate[b * 2]     = e0 * inv;
            Gate[b * 2 + 1] = e1 * inv;
        }
    }
}

__global__ void combine_kernel(const float* __restrict__ Os, const float* __restrict__ Op,
                               const float* __restrict__ Gate, float* __restrict__ Out) {
    size_t i = (size_t)blockIdx.x * 256 + threadIdx.x;
    int b = (int)(i >> 21);
    Out[i] = Gate[b * 2] * Os[i] + Gate[b * 2 + 1] * Op[i];
}

// ---------------- host launcher ----------------
extern "C" void kernel_launch(void* const* d_in, const int* in_sizes, int n_in,
                              void* d_out, int out_size) {
    const float* x    = (const float*)d_in[0];
    const float* Wq_s = (const float*)d_in[1];
    const float* Wk_s = (const float*)d_in[2];
    const float* Wv_s = (const float*)d_in[3];
    const float* Wo_s = (const float*)d_in[4];
    const float* bq_s = (const float*)d_in[5];
    const float* bk_s = (const float*)d_in[6];
    const float* bv_s = (const float*)d_in[7];
    const float* bo_s = (const float*)d_in[8];
    const float* Wq_p = (const float*)d_in[9];
    const float* Wk_p = (const float*)d_in[10];
    const float* Wv_p = (const float*)d_in[11];
    const float* Wo_p = (const float*)d_in[12];
    const float* bo_p = (const float*)d_in[13];
    const float* Wfeat = (const float*)d_in[14];
    const float* Wg   = (const float*)d_in[15];
    const float* bg   = (const float*)d_in[16];
    float* out = (float*)d_out;

    float *Qs, *Ks, *Vs, *Qp, *Kp, *Vp, *Scr, *MrgS, *MrgP, *Os, *Op;
    float *Pq, *Pk, *KVb, *Zb, *Av, *Gt;
    __nv_bfloat16 *Ahi, *Alo, *Whi, *Wlo;
    cudaGetSymbolAddress((void**)&Qs,   g_Qs);
    cudaGetSymbolAddress((void**)&Ks,   g_Ks);
    cudaGetSymbolAddress((void**)&Vs,   g_Vs);
    cudaGetSymbolAddress((void**)&Qp,   g_Qp);
    cudaGetSymbolAddress((void**)&Kp,   g_Kp);
    cudaGetSymbolAddress((void**)&Vp,   g_Vp);
    cudaGetSymbolAddress((void**)&Scr,  g_scores);
    cudaGetSymbolAddress((void**)&MrgS, g_merged_s);
    cudaGetSymbolAddress((void**)&MrgP, g_merged_p);
    cudaGetSymbolAddress((void**)&Os,   g_out_s);
    cudaGetSymbolAddress((void**)&Op,   g_out_p);
    cudaGetSymbolAddress((void**)&Pq,   g_phi_q);
    cudaGetSymbolAddress((void**)&Pk,   g_phi_k);
    cudaGetSymbolAddress((void**)&KVb,  g_kv);
    cudaGetSymbolAddress((void**)&Zb,   g_z);
    cudaGetSymbolAddress((void**)&Av,   g_avg);
    cudaGetSymbolAddress((void**)&Gt,   g_gate);
    cudaGetSymbolAddress((void**)&Ahi,  g_ahi);
    cudaGetSymbolAddress((void**)&Alo,  g_alo);
    cudaGetSymbolAddress((void**)&Whi,  g_wthi);
    cudaGetSymbolAddress((void**)&Wlo,  g_wtlo);

    const int MT = BQ * SQ;                      // 4096 token rows
    const size_t WS = (size_t)EQ * EQ;
    const int NB4 = (MT * EQ) / 1024;

    // ---- conversions for the benign-precision (wmma) path ----
    split_fp32<<<NB4, 256>>>(x, Ahi, Alo);
    // order: Wv_s(0), Wq_p(1), Wk_p(2), Wv_p(3), Wo_s(4), Wo_p(5)
    const float* Wlist[6] = {Wv_s, Wq_p, Wk_p, Wv_p, Wo_s, Wo_p};
    for (int w = 0; w < 6; w++)
        wtrans_split<<<dim3(32, 32), 256>>>(Wlist[w], Whi + w * WS, Wlo + w * WS);

    // ---- selection-critical path: EXACT fp32 (matches round-11 bit behavior) ----
    dim3 sg(EQ / 128, MT / 128);
    sgemm_nn<<<sg, 256>>>(x, Wq_s, bq_s, Qs, MT, EQ, EQ);
    sgemm_nn<<<sg, 256>>>(x, Wk_s, bk_s, Ks, MT, EQ, EQ);

    // ---- benign path projections on tensor cores ----
    dim3 pg(EQ / 128, MT / 128);
    gemm_wmma<<<pg, 256>>>(Ahi, Alo, EQ, Whi + 0*WS, Wlo + 0*WS, EQ, Vs, EQ, EQ);
    gemm_wmma<<<pg, 256>>>(Ahi, Alo, EQ, Whi + 1*WS, Wlo + 1*WS, EQ, Qp, EQ, EQ);
    gemm_wmma<<<pg, 256>>>(Ahi, Alo, EQ, Whi + 2*WS, Wlo + 2*WS, EQ, Kp, EQ, EQ);
    gemm_wmma<<<pg, 256>>>(Ahi, Alo, EQ, Whi + 3*WS, Wlo + 3*WS, EQ, Vp, EQ, EQ);
    bias_add<<<NB4, 256>>>(Vs, bv_s);

    // ---- sparse branch: exact fp32 scores + fused topk/softmax/PV ----
    score_kernel<<<dim3(SQ / 128, SQ / 128, BQ * HQ), 256>>>(Qs, Ks, Scr);
    topk_pv_kernel<<<BQ * HQ * SQ, 256>>>(Scr, Vs, MrgS);
    split_fp32<<<NB4, 256>>>(MrgS, Ahi, Alo);
    gemm_wmma<<<pg, 256>>>(Ahi, Alo, EQ, Whi + 4*WS, Wlo + 4*WS, EQ, Os, EQ, EQ);
    bias_add<<<NB4, 256>>>(Os, bo_s);

    // ---- performer branch ----
    phi_kernel<<<dim3(MQ / 64, SQ / 128, BQ * HQ), 256>>>(Qp, Wfeat, Pq);
    phi_kernel<<<dim3(MQ / 64, SQ / 128, BQ * HQ), 256>>>(Kp, Wfeat, Pk);
    kv_kernel<<<dim3(MQ / 64, BQ * HQ), 256>>>(Pk, Vp, KVb, Zb);
    numden_kernel<<<dim3(SQ / 128, BQ * HQ), 256>>>(Pq, KVb, Zb, MrgP);
    split_fp32<<<NB4, 256>>>(MrgP, Ahi, Alo);
    gemm_wmma<<<pg, 256>>>(Ahi, Alo, EQ, Whi + 5*WS, Wlo + 5*WS, EQ, Op, EQ, EQ);
    bias_add<<<NB4, 256>>>(Op, bo_p);

    // ---- gate + combine ----
    avg_kernel<<<dim3(BQ, EQ / 256), 256>>>(x, Av);
    gate_kernel<<<1, 256>>>(Av, Wg, bg, Gt);
    combine_kernel<<<(BQ * SQ * EQ) / 256, 256>>>(Os, Op, Gt, out);
}

// round 17
// speedup vs baseline: 1.5090x; 1.3652x over previous
#include <cuda_runtime.h>
#include <cuda_bf16.h>
#include <mma.h>
#include <math.h>
#include <stdint.h>

using namespace nvcuda;

// Problem constants
#define BQ 2
#define SQ 2048
#define EQ 1024
#define HQ 16
#define DQ 64
#define MQ 256
#define KTOP 64
#define EPSF 1e-6f

// ---------------- device scratch (no cudaMalloc allowed) ----------------
__device__ float g_Qs[BQ*SQ*EQ];
__device__ float g_Ks[BQ*SQ*EQ];
__device__ float g_Vs[BQ*SQ*EQ];
__device__ float g_Qp[BQ*SQ*EQ];
__device__ float g_Kp[BQ*SQ*EQ];
__device__ float g_Vp[BQ*SQ*EQ];
__device__ float g_scores[(size_t)BQ*HQ*SQ*SQ];      // 512 MB
__device__ float g_merged_s[BQ*SQ*EQ];
__device__ float g_merged_p[BQ*SQ*EQ];
__device__ float g_out_s[BQ*SQ*EQ];
__device__ float g_out_p[BQ*SQ*EQ];
__device__ float g_phi_q[BQ*HQ*SQ*MQ];
__device__ float g_phi_k[BQ*HQ*SQ*MQ];
__device__ float g_kv[BQ*HQ*MQ*DQ];
__device__ float g_kv4[4*BQ*HQ*MQ*DQ];    // s-split partials
__device__ float g_z[BQ*HQ*MQ];
__device__ float g_z4[4*BQ*HQ*MQ];
__device__ float g_avgp[8*BQ*EQ];          // s-split partial column sums
__device__ float g_gate[BQ*2];

// bf16 hi/lo split scratch (off-selection-path GEMMs only)
__device__ __align__(16) __nv_bfloat16 g_ahi[BQ*SQ*EQ];
__device__ __align__(16) __nv_bfloat16 g_alo[BQ*SQ*EQ];
__device__ __align__(16) __nv_bfloat16 g_wthi[6*EQ*EQ];   // transposed weights [n][k]
__device__ __align__(16) __nv_bfloat16 g_wtlo[6*EQ*EQ];

// ---------------- fp32 SGEMM (NN) 128x128x16, 8x8/thread — EXACT path ----------------
__global__ __launch_bounds__(256) void sgemm_nn(const float* __restrict__ A,
                                                const float* __restrict__ Bm,
                                                const float* __restrict__ bias,
                                                float* __restrict__ C,
                                                int Mn, int Nn, int Kn) {
    __shared__ float As[16][132];
    __shared__ float Bs[16][128];
    int tid = threadIdx.x;
    int m0 = blockIdx.y * 128, n0 = blockIdx.x * 128;
    int tx = tid & 15, ty = tid >> 4;
    float acc[8][8];
#pragma unroll
    for (int i = 0; i < 8; i++)
#pragma unroll
        for (int j = 0; j < 8; j++) acc[i][j] = 0.f;

    for (int k0 = 0; k0 < Kn; k0 += 16) {
#pragma unroll
        for (int r = 0; r < 2; r++) {
            int idx = tid + r * 256;
            int ar = idx >> 2;
            int ac = (idx & 3) * 4;
            float4 v = *(const float4*)(A + (size_t)(m0 + ar) * Kn + k0 + ac);
            As[ac + 0][ar] = v.x; As[ac + 1][ar] = v.y;
            As[ac + 2][ar] = v.z; As[ac + 3][ar] = v.w;
        }
#pragma unroll
        for (int r = 0; r < 2; r++) {
            int idx = tid + r * 256;
            int br = idx >> 5;
            int bc = (idx & 31) * 4;
            *(float4*)&Bs[br][bc] = *(const float4*)(Bm + (size_t)(k0 + br) * Nn + n0 + bc);
        }
        __syncthreads();
#pragma unroll
        for (int kk = 0; kk < 16; kk++) {
            float a[8], b[8];
            *(float4*)a       = *(float4*)&As[kk][ty * 8];
            *(float4*)(a + 4) = *(float4*)&As[kk][ty * 8 + 4];
            *(float4*)b       = *(float4*)&Bs[kk][tx * 8];
            *(float4*)(b + 4) = *(float4*)&Bs[kk][tx * 8 + 4];
#pragma unroll
            for (int i = 0; i < 8; i++)
#pragma unroll
                for (int j = 0; j < 8; j++) acc[i][j] += a[i] * b[j];
        }
        __syncthreads();
    }
    float bv[8];
#pragma unroll
    for (int j = 0; j < 8; j++) bv[j] = bias ? bias[n0 + tx * 8 + j] : 0.f;
    float* Cb = C + (size_t)(m0 + ty * 8) * Nn + n0 + tx * 8;
#pragma unroll
    for (int i = 0; i < 8; i++) {
        float4 o0 = make_float4(acc[i][0] + bv[0], acc[i][1] + bv[1], acc[i][2] + bv[2], acc[i][3] + bv[3]);
        float4 o1 = make_float4(acc[i][4] + bv[4], acc[i][5] + bv[5], acc[i][6] + bv[6], acc[i][7] + bv[7]);
        *(float4*)(Cb + (size_t)i * Nn)     = o0;
        *(float4*)(Cb + (size_t)i * Nn + 4) = o1;
    }
}

// ---------------- scores = 0.125 * Q K^T (fp32, EXACT — selection path) ----------------
__global__ __launch_bounds__(256) void score_kernel(const float* __restrict__ Q,
                                                    const float* __restrict__ Kc,
                                                    float* __restrict__ Sc) {
    __shared__ float Qs[32][132];
    __shared__ float Ks[32][132];
    int tid = threadIdx.x;
    int bh = blockIdx.z;
    int b = bh >> 4, h = bh & 15;
    int q0 = blockIdx.y * 128, k0 = blockIdx.x * 128;
    int tx = tid & 15, ty = tid >> 4;
    float acc[8][8];
#pragma unroll
    for (int i = 0; i < 8; i++)
#pragma unroll
        for (int j = 0; j < 8; j++) acc[i][j] = 0.f;

    const float* Qb = Q + ((size_t)b * SQ + q0) * EQ + h * DQ;
    const float* Kb = Kc + ((size_t)b * SQ + k0) * EQ + h * DQ;

    for (int dc = 0; dc < 64; dc += 32) {
#pragma unroll
        for (int r = 0; r < 4; r++) {
            int idx = tid + r * 256;
            int rr = idx >> 3;
            int cc = (idx & 7) * 4;
            float4 qv = *(const float4*)(Qb + (size_t)rr * EQ + dc + cc);
            Qs[cc + 0][rr] = qv.x; Qs[cc + 1][rr] = qv.y;
            Qs[cc + 2][rr] = qv.z; Qs[cc + 3][rr] = qv.w;
            float4 kv = *(const float4*)(Kb + (size_t)rr * EQ + dc + cc);
            Ks[cc + 0][rr] = kv.x; Ks[cc + 1][rr] = kv.y;
            Ks[cc + 2][rr] = kv.z; Ks[cc + 3][rr] = kv.w;
        }
        __syncthreads();
#pragma unroll
        for (int kk = 0; kk < 32; kk++) {
            float a[8], bb[8];
            *(float4*)a        = *(float4*)&Qs[kk][ty * 8];
            *(float4*)(a + 4)  = *(float4*)&Qs[kk][ty * 8 + 4];
            *(float4*)bb       = *(float4*)&Ks[kk][tx * 8];
            *(float4*)(bb + 4) = *(float4*)&Ks[kk][tx * 8 + 4];
#pragma unroll
            for (int i = 0; i < 8; i++)
#pragma unroll
                for (int j = 0; j < 8; j++) acc[i][j] += a[i] * bb[j];
        }
        __syncthreads();
    }
    float* Cb = Sc + ((size_t)bh * SQ + q0) * SQ + k0;
#pragma unroll
    for (int i = 0; i < 8; i++) {
        float4 o0 = make_float4(acc[i][0] * 0.125f, acc[i][1] * 0.125f, acc[i][2] * 0.125f, acc[i][3] * 0.125f);
        float4 o1 = make_float4(acc[i][4] * 0.125f, acc[i][5] * 0.125f, acc[i][6] * 0.125f, acc[i][7] * 0.125f);
        *(float4*)(Cb + (size_t)(ty * 8 + i) * SQ + tx * 8)     = o0;
        *(float4*)(Cb + (size_t)(ty * 8 + i) * SQ + tx * 8 + 4) = o1;
    }
}

// =============== WMMA bf16 split-2 GEMM, cp.async double-buffered ======
#define SLD 48
#define TILE_E (128 * SLD)              // elements per staged tile
#define GW_SMEM (2 * 4 * TILE_E * 2)    // 98304 bytes

__device__ __forceinline__ void cp16(void* s, const void* g) {
    unsigned ss = (unsigned)__cvta_generic_to_shared(s);
    asm volatile("cp.async.cg.shared.global [%0], [%1], 16;" :: "r"(ss), "l"(g));
}

__device__ __forceinline__ void gw_issue(__nv_bfloat16* smq, int ch, int tid,
                                         int m0, int n0, int lda, int ldb,
                                         const __nv_bfloat16* Ahi, const __nv_bfloat16* Alo,
                                         const __nv_bfloat16* Bhi, const __nv_bfloat16* Blo) {
    __nv_bfloat16* base = smq + (ch & 1) * 4 * TILE_E;
    int kc = ch << 5;
#pragma unroll
    for (int it = 0; it < 2; it++) {
        int idx = tid + it * 256;
        int r = idx >> 2, c8 = (idx & 3) * 8;
        size_t ga = (size_t)(m0 + r) * lda + kc + c8;
        size_t gb = (size_t)(n0 + r) * ldb + kc + c8;
        cp16(base + r * SLD + c8,              Ahi + ga);
        cp16(base + TILE_E + r * SLD + c8,     Alo + ga);
        cp16(base + 2 * TILE_E + r * SLD + c8, Bhi + gb);
        cp16(base + 3 * TILE_E + r * SLD + c8, Blo + gb);
    }
    asm volatile("cp.async.commit_group;" ::: "memory");
}

__global__ __launch_bounds__(256, 2) void gemm_wmma(
    const __nv_bfloat16* __restrict__ Ahi, const __nv_bfloat16* __restrict__ Alo, int lda,
    const __nv_bfloat16* __restrict__ Bhi, const __nv_bfloat16* __restrict__ Blo, int ldb,
    float* __restrict__ C, int ldc, int Ktot)
{
    extern __shared__ __align__(128) __nv_bfloat16 smq[];
    int tid = threadIdx.x, wid = tid >> 5;
    int m0 = blockIdx.y * 128, n0 = blockIdx.x * 128;
    int wm = (wid & 3) * 32;
    int wn = (wid >> 2) * 64;

    wmma::fragment<wmma::accumulator, 16, 16, 16, float> acc[2][4];
#pragma unroll
    for (int i = 0; i < 2; i++)
#pragma unroll
        for (int j = 0; j < 4; j++) wmma::fill_fragment(acc[i][j], 0.f);

    int nch = Ktot >> 5;
    gw_issue(smq, 0, tid, m0, n0, lda, ldb, Ahi, Alo, Bhi, Blo);

    for (int ch = 0; ch < nch; ch++) {
        if (ch + 1 < nch) {
            gw_issue(smq, ch + 1, tid, m0, n0, lda, ldb, Ahi, Alo, Bhi, Blo);
            asm volatile("cp.async.wait_group 1;" ::: "memory");
        } else {
            asm volatile("cp.async.wait_group 0;" ::: "memory");
        }
        __syncthreads();

        const __nv_bfloat16* base = smq + (ch & 1) * 4 * TILE_E;
        const __nv_bfloat16* sAh = base;
        const __nv_bfloat16* sAl = base + TILE_E;
        const __nv_bfloat16* sBh = base + 2 * TILE_E;
        const __nv_bfloat16* sBl = base + 3 * TILE_E;

#pragma unroll
        for (int ko = 0; ko < 32; ko += 16) {
            wmma::fragment<wmma::matrix_a, 16, 16, 16, __nv_bfloat16, wmma::row_major> ah[2], al[2];
#pragma unroll
            for (int i = 0; i < 2; i++) {
                wmma::load_matrix_sync(ah[i], sAh + (wm + i * 16) * SLD + ko, SLD);
                wmma::load_matrix_sync(al[i], sAl + (wm + i * 16) * SLD + ko, SLD);
            }
#pragma unroll
            for (int j = 0; j < 4; j++) {
                wmma::fragment<wmma::matrix_b, 16, 16, 16, __nv_bfloat16, wmma::col_major> bh, bl;
                wmma::load_matrix_sync(bh, sBh + (wn + j * 16) * SLD + ko, SLD);
                wmma::load_matrix_sync(bl, sBl + (wn + j * 16) * SLD + ko, SLD);
#pragma unroll
                for (int i = 0; i < 2; i++) {
                    wmma::mma_sync(acc[i][j], ah[i], bh, acc[i][j]);
                    wmma::mma_sync(acc[i][j], ah[i], bl, acc[i][j]);
                    wmma::mma_sync(acc[i][j], al[i], bh, acc[i][j]);
                }
            }
        }
        __syncthreads();
    }

#pragma unroll
    for (int i = 0; i < 2; i++)
#pragma unroll
        for (int j = 0; j < 4; j++)
            wmma::store_matrix_sync(C + (size_t)(m0 + wm + i * 16) * ldc + n0 + wn + j * 16,
                                    acc[i][j], ldc, wmma::mem_row_major);
}

// bias add: C[m][n] += bias[n]
__global__ void bias_add(float* __restrict__ C, const float* __restrict__ bias) {
    size_t i = ((size_t)blockIdx.x * 256 + threadIdx.x) * 4;
    int n = (int)(i & (EQ - 1));
    float4 c = *(float4*)(C + i);
    float4 bv = *(const float4*)(bias + n);
    c.x += bv.x; c.y += bv.y; c.z += bv.z; c.w += bv.w;
    *(float4*)(C + i) = c;
}

// =============== hi/lo conversion kernels ===============
__device__ __forceinline__ void split1(float v, __nv_bfloat16& h, __nv_bfloat16& l) {
    h = __float2bfloat16(v);
    l = __float2bfloat16(v - __bfloat162float(h));
}

__global__ void split_fp32(const float* __restrict__ in,
                           __nv_bfloat16* __restrict__ hi, __nv_bfloat16* __restrict__ lo) {
    size_t i = (size_t)blockIdx.x * 256 + threadIdx.x;
    float4 v = ((const float4*)in)[i];
    __nv_bfloat16 h[4], l[4];
    split1(v.x, h[0], l[0]); split1(v.y, h[1], l[1]);
    split1(v.z, h[2], l[2]); split1(v.w, h[3], l[3]);
    *(uint2*)(hi + i * 4) = *(uint2*)h;
    *(uint2*)(lo + i * 4) = *(uint2*)l;
}

// W[k][n] fp32 -> T[n][k] bf16 hi/lo
__global__ void wtrans_split(const float* __restrict__ W,
                             __nv_bfloat16* __restrict__ Thi, __nv_bfloat16* __restrict__ Tlo) {
    __shared__ float t[32][33];
    int n0 = blockIdx.x * 32, k0 = blockIdx.y * 32;
    int tx = threadIdx.x & 31, ty = threadIdx.x >> 5;
#pragma unroll
    for (int r = 0; r < 32; r += 8)
        t[ty + r][tx] = W[(size_t)(k0 + ty + r) * EQ + n0 + tx];
    __syncthreads();
#pragma unroll
    for (int r = 0; r < 32; r += 8) {
        float v = t[tx][ty + r];
        size_t o = (size_t)(n0 + ty + r) * EQ + k0 + tx;
        __nv_bfloat16 h, l;
        split1(v, h, l);
        Thi[o] = h; Tlo[o] = l;
    }
}

// ---------------- fused top-64 select + masked softmax + P*V gather ----------------
__device__ __forceinline__ unsigned fkey(float f) {
    unsigned u = __float_as_uint(f);
    return (u & 0x80000000u) ? ~u : (u | 0x80000000u);
}

#define CAPL 1024
__global__ __launch_bounds__(256) void topk_pv_kernel(const float* __restrict__ Sc,
                                                      const float* __restrict__ V,
                                                      float* __restrict__ Mrg) {
    __shared__ float row[2048];
    __shared__ unsigned hist[256];
    __shared__ unsigned scanb[256];
    __shared__ float red[256];
    __shared__ int   s_idx[CAPL];
    __shared__ float s_p[CAPL];
    __shared__ float outacc[64];
    __shared__ unsigned s_prefix;
    __shared__ int s_want;
    __shared__ int s_cnt;

    int tid = threadIdx.x;
    int rrow = blockIdx.x;
    int bh = rrow >> 11;
    int q = rrow & 2047;
    int b = bh >> 4, h = bh & 15;

    const float* src = Sc + (size_t)rrow * 2048;
    float lmax = -3.4e38f;
#pragma unroll
    for (int t = 0; t < 2; t++) {
        int i4 = tid + t * 256;
        float4 v = ((const float4*)src)[i4];
        *(float4*)&row[i4 * 4] = v;
        lmax = fmaxf(lmax, fmaxf(fmaxf(v.x, v.y), fmaxf(v.z, v.w)));
    }
    red[tid] = lmax;
    __syncthreads();
    for (int s = 128; s > 0; s >>= 1) {
        if (tid < s) red[tid] = fmaxf(red[tid], red[tid + s]);
        __syncthreads();
    }
    float rowmax = red[0];
    __syncthreads();

    // MSD radix select with parallel suffix scan
    unsigned prefix = 0;
    int want = KTOP;
    for (int pass = 3; pass >= 0; pass--) {
        hist[tid] = 0;
        __syncthreads();
        int shift = pass * 8;
        unsigned himask = (pass == 3) ? 0u : (0xFFFFFFFFu << (8 * (pass + 1)));
#pragma unroll
        for (int t = 0; t < 8; t++) {
            int i = tid + t * 256;
            unsigned u = fkey(row[i]);
            if ((u & himask) == prefix) atomicAdd(&hist[(u >> shift) & 255], 1u);
        }
        __syncthreads();
        // suffix (descending) inclusive scan over 256 bins
        scanb[tid] = hist[tid];
        __syncthreads();
#pragma unroll
        for (int off = 1; off < 256; off <<= 1) {
            unsigned t = (tid + off < 256) ? scanb[tid + off] : 0u;
            __syncthreads();
            scanb[tid] += t;
            __syncthreads();
        }
        unsigned incl = scanb[tid];
        unsigned cumAbove = incl - hist[tid];
        if (incl >= (unsigned)want && cumAbove < (unsigned)want) {
            s_prefix = prefix | ((unsigned)tid << shift);
            s_want = want - (int)cumAbove;
        }
        __syncthreads();
        prefix = s_prefix;
        want = s_want;
        __syncthreads();
    }
    unsigned tk = prefix;

    if (tid == 0) s_cnt = 0;
    __syncthreads();
#pragma unroll
    for (int t = 0; t < 8; t++) {
        int i = tid + t * 256;
        float v = row[i];
        if (fkey(v) >= tk) {
            int p = atomicAdd(&s_cnt, 1);
            if (p < CAPL) { s_idx[p] = i; s_p[p] = expf(v - rowmax); }
        }
    }
    __syncthreads();
    int cnt = s_cnt;

    float* dst = Mrg + ((size_t)(b * SQ + q)) * EQ + h * DQ;
    const float* Vb = V + (size_t)b * SQ * EQ + h * DQ;

    if (cnt <= CAPL) {
        float ps = 0.f;
        for (int j = tid; j < cnt; j += 256) ps += s_p[j];
        red[tid] = ps;
        __syncthreads();
        for (int s = 128; s > 0; s >>= 1) {
            if (tid < s) red[tid] += red[tid + s];
            __syncthreads();
        }
        float sum = red[0];
        __syncthreads();
        // PV gather: 256 threads = 64 d-lanes x 4 j-segments
        int d = tid & 63, seg = tid >> 6;
        float a = 0.f;
        for (int j = seg; j < cnt; j += 4)
            a += s_p[j] * Vb[(size_t)s_idx[j] * EQ + d];
        red[tid] = a;
        __syncthreads();
        if (tid < 64)
            dst[tid] = (red[tid] + red[64 + tid] + red[128 + tid] + red[192 + tid]) / sum;
    } else {
        // pathological tie-overflow fallback (exact, dense)
        if (tid < 64) outacc[tid] = 0.f;
        float ps = 0.f;
#pragma unroll
        for (int t = 0; t < 8; t++) {
            int i = tid + t * 256;
            float v = row[i];
            if (fkey(v) >= tk) ps += expf(v - rowmax);
        }
        red[tid] = ps;
        __syncthreads();
        for (int s = 128; s > 0; s >>= 1) {
            if (tid < s) red[tid] += red[tid + s];
            __syncthreads();
        }
        float sum = red[0];
        int d = tid & 63, seg = tid >> 6;
        float a = 0.f;
        for (int i = seg * 512; i < seg * 512 + 512; i++) {
            float v = row[i];
            if (fkey(v) >= tk) a += expf(v - rowmax) * Vb[(size_t)i * EQ + d];
        }
        atomicAdd(&outacc[d], a);
        __syncthreads();
        if (tid < 64) dst[tid] = outacc[tid] / sum;
    }
}

// ---------------- performer: phi = relu(q @ Wfeat) + eps ----------------
__global__ __launch_bounds__(256) void phi_kernel(const float* __restrict__ Qp,
                                                  const float* __restrict__ Wf,
                                                  float* __restrict__ Phi) {
    __shared__ float Qt[32][132];
    __shared__ float Wt[32][64];
    int tid = threadIdx.x;
    int m0 = blockIdx.x * 64, s0 = blockIdx.y * 128, bh = blockIdx.z;
    int b = bh >> 4, h = bh & 15;
    int tx = tid & 15, ty = tid >> 4;
    float acc[8][4];
#pragma unroll
    for (int i = 0; i < 8; i++)
#pragma unroll
        for (int j = 0; j < 4; j++) acc[i][j] = 0.f;

    const float* Qb = Qp + ((size_t)b * SQ + s0) * EQ + h * DQ;
    for (int dc = 0; dc < 64; dc += 32) {
#pragma unroll
        for (int r = 0; r < 4; r++) {
            int idx = tid + r * 256;
            int rr = idx >> 3;
            int cc = (idx & 7) * 4;
            float4 v = *(const float4*)(Qb + (size_t)rr * EQ + dc + cc);
            Qt[cc + 0][rr] = v.x; Qt[cc + 1][rr] = v.y;
            Qt[cc + 2][rr] = v.z; Qt[cc + 3][rr] = v.w;
        }
#pragma unroll
        for (int r = 0; r < 2; r++) {
            int idx = tid + r * 256;
            int rr = idx >> 4;
            int cc = (idx & 15) * 4;
            *(float4*)&Wt[rr][cc] = *(const float4*)(Wf + (size_t)(dc + rr) * MQ + m0 + cc);
        }
        __syncthreads();
#pragma unroll
        for (int kk = 0; kk < 32; kk++) {
            float a[8], w[4];
            *(float4*)a       = *(float4*)&Qt[kk][ty * 8];
            *(float4*)(a + 4) = *(float4*)&Qt[kk][ty * 8 + 4];
            *(float4*)w       = *(float4*)&Wt[kk][tx * 4];
#pragma unroll
            for (int i = 0; i < 8; i++)
#pragma unroll
                for (int j = 0; j < 4; j++) acc[i][j] += a[i] * w[j];
        }
        __syncthreads();
    }
    float* Pb = Phi + ((size_t)bh * SQ + s0) * MQ + m0;
#pragma unroll
    for (int i = 0; i < 8; i++) {
        float4 o = make_float4(fmaxf(acc[i][0], 0.f) + EPSF, fmaxf(acc[i][1], 0.f) + EPSF,
                               fmaxf(acc[i][2], 0.f) + EPSF, fmaxf(acc[i][3], 0.f) + EPSF);
        *(float4*)(Pb + (size_t)(ty * 8 + i) * MQ + tx * 4) = o;
    }
}

// ---------------- kv partial: s-chunked for parallelism (deterministic) ----------------
__global__ __launch_bounds__(256) void kv_part(const float* __restrict__ Phik,
                                               const float* __restrict__ Vp,
                                               float* __restrict__ KV4,
                                               float* __restrict__ Z4) {
    __shared__ float Ph[16][64];
    __shared__ float Vv[16][64];
    int tid = threadIdx.x;
    int m0 = blockIdx.x * 64, bh = blockIdx.y, sc = blockIdx.z;
    int b = bh >> 4, h = bh & 15;
    int td = tid & 15, tm = tid >> 4;
    float acc[4][4];
    float zacc[4];
#pragma unroll
    for (int i = 0; i < 4; i++) {
        zacc[i] = 0.f;
#pragma unroll
        for (int j = 0; j < 4; j++) acc[i][j] = 0.f;
    }
    int sbeg = sc * (SQ / 4), send = sbeg + (SQ / 4);
    for (int s0 = sbeg; s0 < send; s0 += 16) {
        int rr = tid >> 4, cc = (tid & 15) * 4;
        *(float4*)&Ph[rr][cc] = *(const float4*)(Phik + ((size_t)bh * SQ + s0 + rr) * MQ + m0 + cc);
        *(float4*)&Vv[rr][cc] = *(const float4*)(Vp + ((size_t)(b * SQ + s0 + rr)) * EQ + h * DQ + cc);
        __syncthreads();
#pragma unroll
        for (int ss = 0; ss < 16; ss++) {
            float pm[4], vv[4];
            *(float4*)pm = *(float4*)&Ph[ss][tm * 4];
            *(float4*)vv = *(float4*)&Vv[ss][td * 4];
#pragma unroll
            for (int i = 0; i < 4; i++)
#pragma unroll
                for (int j = 0; j < 4; j++) acc[i][j] += pm[i] * vv[j];
            if (td == 0) {
#pragma unroll
                for (int i = 0; i < 4; i++) zacc[i] += pm[i];
            }
        }
        __syncthreads();
    }
    float* KVo = KV4 + (size_t)sc * (BQ * HQ * MQ * DQ) + (size_t)bh * MQ * DQ;
#pragma unroll
    for (int i = 0; i < 4; i++)
#pragma unroll
        for (int j = 0; j < 4; j++)
            KVo[(size_t)(m0 + tm * 4 + i) * DQ + td * 4 + j] = acc[i][j];
    if (td == 0) {
#pragma unroll
        for (int i = 0; i < 4; i++)
            Z4[(size_t)sc * (BQ * HQ * MQ) + (size_t)bh * MQ + m0 + tm * 4 + i] = zacc[i];
    }
}

__global__ void kv_reduce(const float* __restrict__ KV4, float* __restrict__ KV) {
    size_t i = ((size_t)blockIdx.x * 256 + threadIdx.x) * 4;
    const size_t st = (size_t)BQ * HQ * MQ * DQ;
    float4 a = *(const float4*)(KV4 + i);
    float4 b = *(const float4*)(KV4 + st + i);
    float4 c = *(const float4*)(KV4 + 2 * st + i);
    float4 d = *(const float4*)(KV4 + 3 * st + i);
    float4 o = make_float4(a.x + b.x + c.x + d.x, a.y + b.y + c.y + d.y,
                           a.z + b.z + c.z + d.z, a.w + b.w + c.w + d.w);
    *(float4*)(KV + i) = o;
}

__global__ void z_reduce(const float* __restrict__ Z4, float* __restrict__ Z) {
    int i = blockIdx.x * 256 + threadIdx.x;
    const int st = BQ * HQ * MQ;
    Z[i] = Z4[i] + Z4[st + i] + Z4[2 * st + i] + Z4[3 * st + i];
}

// ---------------- num/den ----------------
__global__ __launch_bounds__(256) void numden_kernel(const float* __restrict__ Phiq,
                                                     const float* __restrict__ KV,
                                                     const float* __restrict__ Z,
                                                     float* __restrict__ Out) {
    __shared__ float Pt[32][132];
    __shared__ float Kv[32][64];
    __shared__ float zk[32];
    int tid = threadIdx.x;
    int s0 = blockIdx.x * 128, bh = blockIdx.y;
    int b = bh >> 4, h = bh & 15;
    int tx = tid & 15, ty = tid >> 4;
    float acc[8][4];
    float den[8];
#pragma unroll
    for (int i = 0; i < 8; i++) {
        den[i] = 0.f;
#pragma unroll
        for (int j = 0; j < 4; j++) acc[i][j] = 0.f;
    }
    for (int kc = 0; kc < MQ; kc += 32) {
#pragma unroll
        for (int r = 0; r < 4; r++) {
            int idx = tid + r * 256;
            int rr = idx >> 3;
            int cc = (idx & 7) * 4;
            float4 v = *(const float4*)(Phiq + ((size_t)bh * SQ + s0 + rr) * MQ + kc + cc);
            Pt[cc + 0][rr] = v.x; Pt[cc + 1][rr] = v.y;
            Pt[cc + 2][rr] = v.z; Pt[cc + 3][rr] = v.w;
        }
#pragma unroll
        for (int r = 0; r < 2; r++) {
            int idx = tid + r * 256;
            int rr = idx >> 4;
            int cc = (idx & 15) * 4;
            *(float4*)&Kv[rr][cc] = *(const float4*)(KV + (size_t)bh * MQ * DQ + (size_t)(kc + rr) * DQ + cc);
        }
        if (tid < 32) zk[tid] = Z[(size_t)bh * MQ + kc + tid];
        __syncthreads();
#pragma unroll
        for (int kk = 0; kk < 32; kk++) {
            float a[8], w[4];
            *(float4*)a       = *(float4*)&Pt[kk][ty * 8];
            *(float4*)(a + 4) = *(float4*)&Pt[kk][ty * 8 + 4];
            *(float4*)w       = *(float4*)&Kv[kk][tx * 4];
            float zz = zk[kk];
#pragma unroll
            for (int i = 0; i < 8; i++) {
                den[i] += a[i] * zz;
#pragma unroll
                for (int j = 0; j < 4; j++) acc[i][j] += a[i] * w[j];
            }
        }
        __syncthreads();
    }
#pragma unroll
    for (int i = 0; i < 8; i++) {
        float inv = 1.f / (den[i] + EPSF);
        float4 o = make_float4(acc[i][0] * inv, acc[i][1] * inv, acc[i][2] * inv, acc[i][3] * inv);
        *(float4*)(Out + ((size_t)(b * SQ + s0 + ty * 8 + i)) * EQ + h * DQ + tx * 4) = o;
    }
}

// ---------------- gating ----------------
// partial column sums over s-chunks of 256
__global__ void avg_part(const float* __restrict__ x, float* __restrict__ Avgp) {
    int b = blockIdx.x;
    int e = blockIdx.y * 256 + threadIdx.x;
    int z = blockIdx.z;
    float s = 0.f;
    int t0 = z * 256;
#pragma unroll 8
    for (int t = t0; t < t0 + 256; t++) s += x[((size_t)b * SQ + t) * EQ + e];
    Avgp[(size_t)(z * BQ + b) * EQ + e] = s;
}

__global__ void gate_kernel(const float* __restrict__ Avgp, const float* __restrict__ Wg,
                            const float* __restrict__ bg, float* __restrict__ Gate) {
    __shared__ float red[256];
    __shared__ float lg[2][2];
    int tid = threadIdx.x;
    float p[2][2] = {{0.f, 0.f}, {0.f, 0.f}};
    for (int e = tid; e < EQ; e += 256) {
        float w0 = Wg[e * 2], w1 = Wg[e * 2 + 1];
        for (int b = 0; b < 2; b++) {
            float a = 0.f;
#pragma unroll
            for (int z = 0; z < 8; z++) a += Avgp[(size_t)(z * BQ + b) * EQ + e];
            a *= (1.f / SQ);
            p[b][0] += a * w0;
            p[b][1] += a * w1;
        }
    }
    for (int b = 0; b < 2; b++)
        for (int j = 0; j < 2; j++) {
            red[tid] = p[b][j];
            __syncthreads();
            for (int s = 128; s > 0; s >>= 1) {
                if (tid < s) red[tid] += red[tid + s];
                __syncthreads();
            }
            if (tid == 0) lg[b][j] = red[0] + bg[j];
            __syncthreads();
        }
    if (tid == 0) {
        for (int b = 0; b < 2; b++) {
            float m = fmaxf(lg[b][0], lg[b][1]);
            float e0 = expf(lg[b][0] - m), e1 = expf(lg[b][1] - m);
            float inv = 1.f / (e0 + e1);
            Gate[b * 2]     = e0 * inv;
            Gate[b * 2 + 1] = e1 * inv;
        }
    }
}

__global__ void combine_kernel(const float* __restrict__ Os, const float* __restrict__ Op,
                               const float* __restrict__ Gate, float* __restrict__ Out) {
    size_t i = (size_t)blockIdx.x * 256 + threadIdx.x;
    int b = (int)(i >> 21);
    Out[i] = Gate[b * 2] * Os[i] + Gate[b * 2 + 1] * Op[i];
}

// ---------------- host launcher ----------------
extern "C" void kernel_launch(void* const* d_in, const int* in_sizes, int n_in,
                              void* d_out, int out_size) {
    const float* x    = (const float*)d_in[0];
    const float* Wq_s = (const float*)d_in[1];
    const float* Wk_s = (const float*)d_in[2];
    const float* Wv_s = (const float*)d_in[3];
    const float* Wo_s = (const float*)d_in[4];
    const float* bq_s = (const float*)d_in[5];
    const float* bk_s = (const float*)d_in[6];
    const float* bv_s = (const float*)d_in[7];
    const float* bo_s = (const float*)d_in[8];
    const float* Wq_p = (const float*)d_in[9];
    const float* Wk_p = (const float*)d_in[10];
    const float* Wv_p = (const float*)d_in[11];
    const float* Wo_p = (const float*)d_in[12];
    const float* bo_p = (const float*)d_in[13];
    const float* Wfeat = (const float*)d_in[14];
    const float* Wg   = (const float*)d_in[15];
    const float* bg   = (const float*)d_in[16];
    float* out = (float*)d_out;

    float *Qs, *Ks, *Vs, *Qp, *Kp, *Vp, *Scr, *MrgS, *MrgP, *Os, *Op;
    float *Pq, *Pk, *KVb, *KV4, *Zb, *Z4, *Avp, *Gt;
    __nv_bfloat16 *Ahi, *Alo, *Whi, *Wlo;
    cudaGetSymbolAddress((void**)&Qs,   g_Qs);
    cudaGetSymbolAddress((void**)&Ks,   g_Ks);
    cudaGetSymbolAddress((void**)&Vs,   g_Vs);
    cudaGetSymbolAddress((void**)&Qp,   g_Qp);
    cudaGetSymbolAddress((void**)&Kp,   g_Kp);
    cudaGetSymbolAddress((void**)&Vp,   g_Vp);
    cudaGetSymbolAddress((void**)&Scr,  g_scores);
    cudaGetSymbolAddress((void**)&MrgS, g_merged_s);
    cudaGetSymbolAddress((void**)&MrgP, g_merged_p);
    cudaGetSymbolAddress((void**)&Os,   g_out_s);
    cudaGetSymbolAddress((void**)&Op,   g_out_p);
    cudaGetSymbolAddress((void**)&Pq,   g_phi_q);
    cudaGetSymbolAddress((void**)&Pk,   g_phi_k);
    cudaGetSymbolAddress((void**)&KVb,  g_kv);
    cudaGetSymbolAddress((void**)&KV4,  g_kv4);
    cudaGetSymbolAddress((void**)&Zb,   g_z);
    cudaGetSymbolAddress((void**)&Z4,   g_z4);
    cudaGetSymbolAddress((void**)&Avp,  g_avgp);
    cudaGetSymbolAddress((void**)&Gt,   g_gate);
    cudaGetSymbolAddress((void**)&Ahi,  g_ahi);
    cudaGetSymbolAddress((void**)&Alo,  g_alo);
    cudaGetSymbolAddress((void**)&Whi,  g_wthi);
    cudaGetSymbolAddress((void**)&Wlo,  g_wtlo);

    cudaFuncSetAttribute(gemm_wmma, cudaFuncAttributeMaxDynamicSharedMemorySize, GW_SMEM);

    const int MT = BQ * SQ;                      // 4096 token rows
    const size_t WS = (size_t)EQ * EQ;
    const int NB4 = (MT * EQ) / 1024;

    // ---- conversions for the benign-precision (wmma) path ----
    split_fp32<<<NB4, 256>>>(x, Ahi, Alo);
    // order: Wv_s(0), Wq_p(1), Wk_p(2), Wv_p(3), Wo_s(4), Wo_p(5)
    const float* Wlist[6] = {Wv_s, Wq_p, Wk_p, Wv_p, Wo_s, Wo_p};
    for (int w = 0; w < 6; w++)
        wtrans_split<<<dim3(32, 32), 256>>>(Wlist[w], Whi + w * WS, Wlo + w * WS);

    // ---- selection-critical path: EXACT fp32 ----
    dim3 sg(EQ / 128, MT / 128);
    sgemm_nn<<<sg, 256>>>(x, Wq_s, bq_s, Qs, MT, EQ, EQ);
    sgemm_nn<<<sg, 256>>>(x, Wk_s, bk_s, Ks, MT, EQ, EQ);

    // ---- benign path projections on tensor cores (double-buffered) ----
    dim3 pg(EQ / 128, MT / 128);
    gemm_wmma<<<pg, 256, GW_SMEM>>>(Ahi, Alo, EQ, Whi + 0*WS, Wlo + 0*WS, EQ, Vs, EQ, EQ);
    gemm_wmma<<<pg, 256, GW_SMEM>>>(Ahi, Alo, EQ, Whi + 1*WS, Wlo + 1*WS, EQ, Qp, EQ, EQ);
    gemm_wmma<<<pg, 256, GW_SMEM>>>(Ahi, Alo, EQ, Whi + 2*WS, Wlo + 2*WS, EQ, Kp, EQ, EQ);
    gemm_wmma<<<pg, 256, GW_SMEM>>>(Ahi, Alo, EQ, Whi + 3*WS, Wlo + 3*WS, EQ, Vp, EQ, EQ);
    bias_add<<<NB4, 256>>>(Vs, bv_s);

    // ---- sparse branch: exact fp32 scores + fused topk/softmax/PV ----
    score_kernel<<<dim3(SQ / 128, SQ / 128, BQ * HQ), 256>>>(Qs, Ks, Scr);
    topk_pv_kernel<<<BQ * HQ * SQ, 256>>>(Scr, Vs, MrgS);
    split_fp32<<<NB4, 256>>>(MrgS, Ahi, Alo);
    gemm_wmma<<<pg, 256, GW_SMEM>>>(Ahi, Alo, EQ, Whi + 4*WS, Wlo + 4*WS, EQ, Os, EQ, EQ);
    bias_add<<<NB4, 256>>>(Os, bo_s);

    // ---- performer branch ----
    phi_kernel<<<dim3(MQ / 64, SQ / 128, BQ * HQ), 256>>>(Qp, Wfeat, Pq);
    phi_kernel<<<dim3(MQ / 64, SQ / 128, BQ * HQ), 256>>>(Kp, Wfeat, Pk);
    kv_part<<<dim3(MQ / 64, BQ * HQ, 4), 256>>>(Pk, Vp, KV4, Z4);
    kv_reduce<<<(BQ * HQ * MQ * DQ) / 1024, 256>>>(KV4, KVb);
    z_reduce<<<(BQ * HQ * MQ) / 256, 256>>>(Z4, Zb);
    numden_kernel<<<dim3(SQ / 128, BQ * HQ), 256>>>(Pq, KVb, Zb, MrgP);
    split_fp32<<<NB4, 256>>>(MrgP, Ahi, Alo);
    gemm_wmma<<<pg, 256, GW_SMEM>>>(Ahi, Alo, EQ, Whi + 5*WS, Wlo + 5*WS, EQ, Op, EQ, EQ);
    bias_add<<<NB4, 256>>>(Op, bo_p);

    // ---- gate + combine ----
    avg_part<<<dim3(BQ, EQ / 256, 8), 256>>>(x, Avp);
    gate_kernel<<<1, 256>>>(Avp, Wg, bg, Gt);
    combine_kernel<<<(BQ * SQ * EQ) / 256, 256>>>(Os, Op, Gt, out);
}